// round 1
// baseline (speedup 1.0000x reference)
#include <cuda_runtime.h>
#include <math.h>

#define B_ 4
#define S_ 2048
#define D_ 512
#define H_ 8
#define HD 64
#define M_ (B_*S_)     // 8192 rows total
#define EPS_ 1e-5f

// Scratch (allocation-free rule: __device__ globals)
__device__ float g_vin[(size_t)M_*D_];
__device__ float g_q  [(size_t)M_*D_];
__device__ float g_k  [(size_t)M_*D_];
__device__ float g_v  [(size_t)M_*D_];
__device__ float g_att[(size_t)M_*D_];

// ---------------------------------------------------------------------------
// LayerNorm: one block (128 threads) per row of 512. Optional residual add.
// ---------------------------------------------------------------------------
__global__ __launch_bounds__(128) void ln_kernel(
    const float* __restrict__ x, const float* __restrict__ res,
    const float* __restrict__ gamma, const float* __restrict__ beta,
    float* __restrict__ y)
{
    const int row = blockIdx.x;
    const int tid = threadIdx.x;               // 0..127, 4 floats each
    const float4* x4 = reinterpret_cast<const float4*>(x + (size_t)row * D_);
    float4 v = x4[tid];
    if (res) {
        const float4* r4 = reinterpret_cast<const float4*>(res + (size_t)row * D_);
        float4 r = r4[tid];
        v.x += r.x; v.y += r.y; v.z += r.z; v.w += r.w;
    }
    float s  = v.x + v.y + v.z + v.w;
    float ss = v.x*v.x + v.y*v.y + v.z*v.z + v.w*v.w;
    #pragma unroll
    for (int o = 16; o > 0; o >>= 1) {
        s  += __shfl_xor_sync(0xffffffffu, s,  o);
        ss += __shfl_xor_sync(0xffffffffu, ss, o);
    }
    __shared__ float sb[4], ssb[4];
    const int w = tid >> 5;
    if ((tid & 31) == 0) { sb[w] = s; ssb[w] = ss; }
    __syncthreads();
    s  = sb[0]  + sb[1]  + sb[2]  + sb[3];
    ss = ssb[0] + ssb[1] + ssb[2] + ssb[3];
    const float mu   = s * (1.0f / D_);
    const float var  = ss * (1.0f / D_) - mu * mu;
    const float rstd = rsqrtf(var + EPS_);
    const float4 g = reinterpret_cast<const float4*>(gamma)[tid];
    const float4 b = reinterpret_cast<const float4*>(beta )[tid];
    float4 o;
    o.x = (v.x - mu) * rstd * g.x + b.x;
    o.y = (v.y - mu) * rstd * g.y + b.y;
    o.z = (v.z - mu) * rstd * g.z + b.z;
    o.w = (v.w - mu) * rstd * g.w + b.w;
    reinterpret_cast<float4*>(y + (size_t)row * D_)[tid] = o;
}

// ---------------------------------------------------------------------------
// NT GEMM: C[m,n] = sum_k A[m,k] * W[n,k].  M=8192, N=K=512.
// 128x128x16 block tile, 256 threads, 8x8 register tile per thread.
// ---------------------------------------------------------------------------
#define BM 128
#define BN 128
#define BK 16

__global__ __launch_bounds__(256) void gemm_nt(
    const float* __restrict__ A, const float* __restrict__ W,
    float* __restrict__ C)
{
    __shared__ float As[BK][BM + 4];
    __shared__ float Ws[BK][BN + 4];
    const int m0 = blockIdx.y * BM;
    const int n0 = blockIdx.x * BN;
    const int tid = threadIdx.x;
    const int tx = tid & 15;      // n sub-block
    const int ty = tid >> 4;      // m sub-block

    float acc[8][8];
    #pragma unroll
    for (int i = 0; i < 8; i++)
        #pragma unroll
        for (int j = 0; j < 8; j++) acc[i][j] = 0.f;

    for (int k0 = 0; k0 < D_; k0 += BK) {
        #pragma unroll
        for (int l = 0; l < 2; l++) {
            const int idx = tid + l * 256;       // 0..511
            const int r  = idx >> 2;             // 0..127
            const int kg = (idx & 3) * 4;        // 0,4,8,12
            float4 a = *reinterpret_cast<const float4*>(&A[(size_t)(m0 + r) * D_ + k0 + kg]);
            As[kg+0][r] = a.x; As[kg+1][r] = a.y; As[kg+2][r] = a.z; As[kg+3][r] = a.w;
            float4 w = *reinterpret_cast<const float4*>(&W[(size_t)(n0 + r) * D_ + k0 + kg]);
            Ws[kg+0][r] = w.x; Ws[kg+1][r] = w.y; Ws[kg+2][r] = w.z; Ws[kg+3][r] = w.w;
        }
        __syncthreads();
        #pragma unroll
        for (int kk = 0; kk < BK; kk++) {
            float a[8], b[8];
            #pragma unroll
            for (int i = 0; i < 8; i++) a[i] = As[kk][ty*8 + i];
            #pragma unroll
            for (int j = 0; j < 8; j++) b[j] = Ws[kk][tx*8 + j];
            #pragma unroll
            for (int i = 0; i < 8; i++)
                #pragma unroll
                for (int j = 0; j < 8; j++)
                    acc[i][j] = fmaf(a[i], b[j], acc[i][j]);
        }
        __syncthreads();
    }
    #pragma unroll
    for (int i = 0; i < 8; i++) {
        float4* crow = reinterpret_cast<float4*>(&C[(size_t)(m0 + ty*8 + i) * D_ + n0 + tx*8]);
        crow[0] = make_float4(acc[i][0], acc[i][1], acc[i][2], acc[i][3]);
        crow[1] = make_float4(acc[i][4], acc[i][5], acc[i][6], acc[i][7]);
    }
}

// ---------------------------------------------------------------------------
// Attention. Quirk: scores[i,j] = dot(K_i, Q_j), softmax over j, out = P @ V.
// One block per (bh, 64-row i-tile); streams j in 64-wide tiles with online
// softmax. 256 threads: 16x16 grid, each thread owns a 4(i) x 4(j/d) tile.
// ---------------------------------------------------------------------------
#define BI 64
#define BJ 64
#define LDS_PAD 68
#define ATTN_SMEM (3 * 64 * LDS_PAD * (int)sizeof(float))

__global__ __launch_bounds__(256) void attn_kernel(
    const float* __restrict__ Q, const float* __restrict__ K,
    const float* __restrict__ V, float* __restrict__ O)
{
    extern __shared__ float sm[];
    float (*Ks)[LDS_PAD] = (float(*)[LDS_PAD])(sm);
    float (*Qs)[LDS_PAD] = (float(*)[LDS_PAD])(sm + 64 * LDS_PAD);      // reused as P
    float (*Vs)[LDS_PAD] = (float(*)[LDS_PAD])(sm + 2 * 64 * LDS_PAD);

    const int it = blockIdx.x;             // i-tile (0..31)
    const int bh = blockIdx.y;             // 0..31
    const int b  = bh / H_, h = bh % H_;
    const size_t base = (size_t)b * S_ * D_ + (size_t)h * HD;
    const int i0 = it * BI;
    const int tid = threadIdx.x;
    const int tx = tid & 15;
    const int ty = tid >> 4;

    // load K tile once (64 rows x 64 cols)
    #pragma unroll
    for (int l = 0; l < 4; l++) {
        const int idx = tid + l * 256;     // 0..1023
        const int r = idx >> 4;
        const int c = (idx & 15) * 4;
        *reinterpret_cast<float4*>(&Ks[r][c]) =
            *reinterpret_cast<const float4*>(&K[base + (size_t)(i0 + r) * D_ + c]);
    }

    float m[4], lsum[4], o[4][4];
    #pragma unroll
    for (int i = 0; i < 4; i++) {
        m[i] = -1e30f; lsum[i] = 0.f;
        #pragma unroll
        for (int j = 0; j < 4; j++) o[i][j] = 0.f;
    }
    __syncthreads();

    for (int jt = 0; jt < S_ / BJ; jt++) {
        const int j0 = jt * BJ;
        #pragma unroll
        for (int l = 0; l < 4; l++) {
            const int idx = tid + l * 256;
            const int r = idx >> 4;
            const int c = (idx & 15) * 4;
            *reinterpret_cast<float4*>(&Qs[r][c]) =
                *reinterpret_cast<const float4*>(&Q[base + (size_t)(j0 + r) * D_ + c]);
            *reinterpret_cast<float4*>(&Vs[r][c]) =
                *reinterpret_cast<const float4*>(&V[base + (size_t)(j0 + r) * D_ + c]);
        }
        __syncthreads();

        // S tile: s[i][j] = dot(K_{i0+ty*4+i}, Q_{j0+tx*4+j})
        float s[4][4];
        #pragma unroll
        for (int i = 0; i < 4; i++)
            #pragma unroll
            for (int j = 0; j < 4; j++) s[i][j] = 0.f;
        #pragma unroll 4
        for (int d = 0; d < HD; d++) {
            float a[4], q[4];
            #pragma unroll
            for (int i = 0; i < 4; i++) a[i] = Ks[ty*4 + i][d];
            #pragma unroll
            for (int j = 0; j < 4; j++) q[j] = Qs[tx*4 + j][d];
            #pragma unroll
            for (int i = 0; i < 4; i++)
                #pragma unroll
                for (int j = 0; j < 4; j++)
                    s[i][j] = fmaf(a[i], q[j], s[i][j]);
        }

        // online softmax update per owned row (replicated over tx group)
        #pragma unroll
        for (int i = 0; i < 4; i++) {
            float mx = fmaxf(fmaxf(s[i][0], s[i][1]), fmaxf(s[i][2], s[i][3]));
            #pragma unroll
            for (int off = 8; off > 0; off >>= 1)
                mx = fmaxf(mx, __shfl_xor_sync(0xffffffffu, mx, off));
            const float mnew  = fmaxf(m[i], mx);
            const float alpha = __expf(m[i] - mnew);
            float rs = 0.f;
            #pragma unroll
            for (int j = 0; j < 4; j++) {
                s[i][j] = __expf(s[i][j] - mnew);
                rs += s[i][j];
            }
            #pragma unroll
            for (int off = 8; off > 0; off >>= 1)
                rs += __shfl_xor_sync(0xffffffffu, rs, off);
            lsum[i] = lsum[i] * alpha + rs;
            m[i] = mnew;
            #pragma unroll
            for (int j = 0; j < 4; j++) o[i][j] *= alpha;
        }

        __syncthreads();   // everyone done reading Qs
        #pragma unroll
        for (int i = 0; i < 4; i++)
            #pragma unroll
            for (int j = 0; j < 4; j++)
                Qs[ty*4 + i][tx*4 + j] = s[i][j];   // P tile
        __syncthreads();

        // O += P @ V   (o[i][dd], dd = tx*4..)
        #pragma unroll 4
        for (int jj = 0; jj < BJ; jj++) {
            float p[4], vv[4];
            #pragma unroll
            for (int i = 0; i < 4; i++) p[i] = Qs[ty*4 + i][jj];
            #pragma unroll
            for (int dd = 0; dd < 4; dd++) vv[dd] = Vs[jj][tx*4 + dd];
            #pragma unroll
            for (int i = 0; i < 4; i++)
                #pragma unroll
                for (int dd = 0; dd < 4; dd++)
                    o[i][dd] = fmaf(p[i], vv[dd], o[i][dd]);
        }
        __syncthreads();   // before next tile overwrites Qs/Vs
    }

    #pragma unroll
    for (int i = 0; i < 4; i++) {
        const float inv = 1.0f / lsum[i];
        float4 r = make_float4(o[i][0]*inv, o[i][1]*inv, o[i][2]*inv, o[i][3]*inv);
        *reinterpret_cast<float4*>(&O[base + (size_t)(i0 + ty*4 + i) * D_ + tx*4]) = r;
    }
}

// ---------------------------------------------------------------------------
extern "C" void kernel_launch(void* const* d_in, const int* in_sizes, int n_in,
                              void* d_out, int out_size)
{
    const float* seq_k = (const float*)d_in[0];
    const float* seq_q = (const float*)d_in[1];
    const float* seq_v = (const float*)d_in[2];
    const float* W1    = (const float*)d_in[3];
    const float* W2    = (const float*)d_in[4];
    const float* W3    = (const float*)d_in[5];
    const float* gamma = (const float*)d_in[6];
    const float* beta  = (const float*)d_in[7];
    float* out = (float*)d_out;

    float *vin, *q, *k, *v, *att;
    cudaGetSymbolAddress((void**)&vin, g_vin);
    cudaGetSymbolAddress((void**)&q,   g_q);
    cudaGetSymbolAddress((void**)&k,   g_k);
    cudaGetSymbolAddress((void**)&v,   g_v);
    cudaGetSymbolAddress((void**)&att, g_att);

    // 1) v_in = LN(seq_v)
    ln_kernel<<<M_, 128>>>(seq_v, nullptr, gamma, beta, vin);

    // 2) q = seq_q @ W1^T ; k = seq_k @ W2^T ; v = v_in @ W3^T
    dim3 ggrid(D_ / BN, M_ / BM);
    gemm_nt<<<ggrid, 256>>>(seq_q, W1, q);
    gemm_nt<<<ggrid, 256>>>(seq_k, W2, k);
    gemm_nt<<<ggrid, 256>>>(vin,   W3, v);

    // 3) attention (scores = K@Q^T, softmax over j, P@V)
    cudaFuncSetAttribute(attn_kernel, cudaFuncAttributeMaxDynamicSharedMemorySize, ATTN_SMEM);
    attn_kernel<<<dim3(S_ / BI, B_ * H_), 256, ATTN_SMEM>>>(q, k, v, att);

    // 4) out = LN(att + v_in)
    ln_kernel<<<M_, 128>>>(att, vin, gamma, beta, out);
}

// round 2
// speedup vs baseline: 1.5321x; 1.5321x over previous
#include <cuda_runtime.h>
#include <math.h>

#define B_ 4
#define S_ 2048
#define D_ 512
#define H_ 8
#define HD 64
#define M_ (B_*S_)
#define EPS_ 1e-5f

// Scratch (allocation-free rule: __device__ globals)
__device__ float g_vin[(size_t)M_*D_];
__device__ float g_q  [(size_t)M_*D_];
__device__ float g_k  [(size_t)M_*D_];
__device__ float g_v  [(size_t)M_*D_];
__device__ float g_att[(size_t)M_*D_];

// ---------------------------------------------------------------------------
// f32x2 packed-math helpers (Blackwell FFMA2 path — ptxas never emits this
// from plain C; it's the only way to reach 128 fp32 FMA/cyc/SM).
// ---------------------------------------------------------------------------
typedef unsigned long long ull;

__device__ __forceinline__ unsigned smem_u32(const void* p) {
    unsigned r;
    asm("{ .reg .u64 t; cvta.to.shared.u64 t, %1; cvt.u32.u64 %0, t; }"
        : "=r"(r) : "l"(p));
    return r;
}
__device__ __forceinline__ ull lds64(unsigned a) {
    ull v;
    asm volatile("ld.shared.b64 %0, [%1];" : "=l"(v) : "r"(a));
    return v;
}
__device__ __forceinline__ void sts64(unsigned a, ull v) {
    asm volatile("st.shared.b64 [%0], %1;" :: "r"(a), "l"(v));
}
__device__ __forceinline__ ull pk2(float lo, float hi) {
    ull v;
    asm("mov.b64 %0, {%1, %2};" : "=l"(v) : "f"(lo), "f"(hi));
    return v;
}
__device__ __forceinline__ void upk2(ull v, float& lo, float& hi) {
    asm("mov.b64 {%0, %1}, %2;" : "=f"(lo), "=f"(hi) : "l"(v));
}
__device__ __forceinline__ void fma2(ull& d, ull a, ull b) {
    asm("fma.rn.f32x2 %0, %1, %2, %0;" : "+l"(d) : "l"(a), "l"(b));
}
__device__ __forceinline__ void mul2(ull& d, ull a) {
    asm("mul.rn.f32x2 %0, %0, %1;" : "+l"(d) : "l"(a));
}

// ---------------------------------------------------------------------------
// LayerNorm: one block (128 threads) per row of 512. Optional residual add.
// ---------------------------------------------------------------------------
__global__ __launch_bounds__(128) void ln_kernel(
    const float* __restrict__ x, const float* __restrict__ res,
    const float* __restrict__ gamma, const float* __restrict__ beta,
    float* __restrict__ y)
{
    const int row = blockIdx.x;
    const int tid = threadIdx.x;
    const float4* x4 = reinterpret_cast<const float4*>(x + (size_t)row * D_);
    float4 v = x4[tid];
    if (res) {
        const float4* r4 = reinterpret_cast<const float4*>(res + (size_t)row * D_);
        float4 r = r4[tid];
        v.x += r.x; v.y += r.y; v.z += r.z; v.w += r.w;
    }
    float s  = v.x + v.y + v.z + v.w;
    float ss = v.x*v.x + v.y*v.y + v.z*v.z + v.w*v.w;
    #pragma unroll
    for (int o = 16; o > 0; o >>= 1) {
        s  += __shfl_xor_sync(0xffffffffu, s,  o);
        ss += __shfl_xor_sync(0xffffffffu, ss, o);
    }
    __shared__ float sb[4], ssb[4];
    const int w = tid >> 5;
    if ((tid & 31) == 0) { sb[w] = s; ssb[w] = ss; }
    __syncthreads();
    s  = sb[0]  + sb[1]  + sb[2]  + sb[3];
    ss = ssb[0] + ssb[1] + ssb[2] + ssb[3];
    const float mu   = s * (1.0f / D_);
    const float var  = ss * (1.0f / D_) - mu * mu;
    const float rstd = rsqrtf(var + EPS_);
    const float4 g = reinterpret_cast<const float4*>(gamma)[tid];
    const float4 b = reinterpret_cast<const float4*>(beta )[tid];
    float4 o;
    o.x = (v.x - mu) * rstd * g.x + b.x;
    o.y = (v.y - mu) * rstd * g.y + b.y;
    o.z = (v.z - mu) * rstd * g.z + b.z;
    o.w = (v.w - mu) * rstd * g.w + b.w;
    reinterpret_cast<float4*>(y + (size_t)row * D_)[tid] = o;
}

// ---------------------------------------------------------------------------
// NT GEMM with FFMA2: C[m,n] = sum_k A[m,k] * W[n,k].  M=8192, N=K=512.
// 128x128x16 tile, 256 threads. Thread owns m-rows ty*8+{2ip,2ip+1} (packed
// f32x2 pairs) x n-cols tx+16*jg (strided -> conflict-free smem reads).
// ---------------------------------------------------------------------------
#define BM 128
#define BN 128
#define BK 16
#define GP 132   // padded row length (floats)

__global__ __launch_bounds__(256, 2) void gemm_nt(
    const float* __restrict__ A, const float* __restrict__ W,
    float* __restrict__ C)
{
    __shared__ __align__(16) float As[BK][GP];
    __shared__ __align__(16) float Ws[BK][GP];
    const unsigned asb = smem_u32(&As[0][0]);
    const int m0 = blockIdx.y * BM;
    const int n0 = blockIdx.x * BN;
    const int tid = threadIdx.x;
    const int tx = tid & 15;
    const int ty = tid >> 4;

    ull acc2[4][8];
    #pragma unroll
    for (int ip = 0; ip < 4; ip++)
        #pragma unroll
        for (int jg = 0; jg < 8; jg++) acc2[ip][jg] = 0ull;

    for (int k0 = 0; k0 < D_; k0 += BK) {
        #pragma unroll
        for (int l = 0; l < 2; l++) {
            const int idx = tid + l * 256;       // 0..511
            const int r  = idx >> 2;             // 0..127
            const int kg = (idx & 3) * 4;        // 0,4,8,12
            float4 a = *reinterpret_cast<const float4*>(&A[(size_t)(m0 + r) * D_ + k0 + kg]);
            As[kg+0][r] = a.x; As[kg+1][r] = a.y; As[kg+2][r] = a.z; As[kg+3][r] = a.w;
            float4 w = *reinterpret_cast<const float4*>(&W[(size_t)(n0 + r) * D_ + k0 + kg]);
            Ws[kg+0][r] = w.x; Ws[kg+1][r] = w.y; Ws[kg+2][r] = w.z; Ws[kg+3][r] = w.w;
        }
        __syncthreads();
        #pragma unroll
        for (int kk = 0; kk < BK; kk++) {
            ull a2[4];
            #pragma unroll
            for (int ip = 0; ip < 4; ip++)
                a2[ip] = lds64(asb + 4u * (kk * GP + ty * 8 + 2 * ip));
            ull bd[8];
            #pragma unroll
            for (int jg = 0; jg < 8; jg++) {
                float b = Ws[kk][tx + 16 * jg];
                bd[jg] = pk2(b, b);
            }
            #pragma unroll
            for (int ip = 0; ip < 4; ip++)
                #pragma unroll
                for (int jg = 0; jg < 8; jg++)
                    fma2(acc2[ip][jg], a2[ip], bd[jg]);
        }
        __syncthreads();
    }
    #pragma unroll
    for (int ip = 0; ip < 4; ip++) {
        const int r = m0 + ty * 8 + 2 * ip;
        #pragma unroll
        for (int jg = 0; jg < 8; jg++) {
            float lo, hi;
            upk2(acc2[ip][jg], lo, hi);
            const int cc = n0 + tx + 16 * jg;
            C[(size_t)r * D_ + cc]       = lo;
            C[(size_t)(r+1) * D_ + cc]   = hi;
        }
    }
}

// ---------------------------------------------------------------------------
// Attention (FFMA2). scores[i,j] = dot(K_i, Q_j), softmax over j, out = P@V.
// Block = (bh, 128-row i-tile). 256 threads. Thread owns i-rows ty*8+{2ip,2ip+1}
// (f32x2 row pairs) x j-cols tx+16*jj (strided, conflict-free).
// Smem: Kst (transposed K, d-major), Qs (row-major pad 65), Vs (pad 68),
//       Ps (j-major, i contiguous for b64 loads, pad 132).
// ---------------------------------------------------------------------------
#define BI 128
#define BJ 128
#define AP_K 132
#define AP_Q 65
#define AP_V 68
#define AP_P 132
#define OQ_ (64 * AP_K)                 // 8448
#define OV_ (OQ_ + BJ * AP_Q)           // 16768
#define OP_ (OV_ + BJ * AP_V)           // 25472
#define ATTN_FLOATS (OP_ + BJ * AP_P)   // 42368
#define ATTN_SMEM (ATTN_FLOATS * (int)sizeof(float))

__global__ __launch_bounds__(256, 1) void attn_kernel(
    const float* __restrict__ Q, const float* __restrict__ K,
    const float* __restrict__ V, float* __restrict__ O)
{
    extern __shared__ float sm[];
    const unsigned sb = smem_u32(sm);

    const int it = blockIdx.x;             // i-tile (0..15)
    const int bh = blockIdx.y;             // 0..31
    const int b  = bh / H_, h = bh % H_;
    const size_t base = (size_t)b * S_ * D_ + (size_t)h * HD;
    const int i0 = it * BI;
    const int tid = threadIdx.x;
    const int tx = tid & 15;
    const int ty = tid >> 4;

    // Load + transpose K tile (128 x 64) -> Kst[d][i]
    #pragma unroll
    for (int l = 0; l < 8; l++) {
        const int idx = tid + l * 256;     // 0..2047
        const int r = idx >> 4;            // 0..127
        const int c = (idx & 15) * 4;      // 0..60
        float4 kv = *reinterpret_cast<const float4*>(&K[base + (size_t)(i0 + r) * D_ + c]);
        sm[(c+0)*AP_K + r] = kv.x;
        sm[(c+1)*AP_K + r] = kv.y;
        sm[(c+2)*AP_K + r] = kv.z;
        sm[(c+3)*AP_K + r] = kv.w;
    }

    ull o2[4][4];
    float m[8], lsum[8];
    #pragma unroll
    for (int ip = 0; ip < 4; ip++)
        #pragma unroll
        for (int c = 0; c < 4; c++) o2[ip][c] = 0ull;
    #pragma unroll
    for (int i = 0; i < 8; i++) { m[i] = -1e30f; lsum[i] = 0.f; }

    for (int jt = 0; jt < S_ / BJ; jt++) {
        const int j0 = jt * BJ;
        // load Q (scatter scalar, pad 65) and V (float4, pad 68)
        #pragma unroll
        for (int l = 0; l < 8; l++) {
            const int idx = tid + l * 256;
            const int r = idx >> 4;
            const int c = (idx & 15) * 4;
            float4 qv = *reinterpret_cast<const float4*>(&Q[base + (size_t)(j0 + r) * D_ + c]);
            sm[OQ_ + r*AP_Q + c + 0] = qv.x;
            sm[OQ_ + r*AP_Q + c + 1] = qv.y;
            sm[OQ_ + r*AP_Q + c + 2] = qv.z;
            sm[OQ_ + r*AP_Q + c + 3] = qv.w;
            float4 vv = *reinterpret_cast<const float4*>(&V[base + (size_t)(j0 + r) * D_ + c]);
            *reinterpret_cast<float4*>(&sm[OV_ + r*AP_V + c]) = vv;
        }
        __syncthreads();

        // ---- S = K @ Q^T tile: s2[ip][jj] packs rows (2ip, 2ip+1) ----
        ull s2[4][8];
        #pragma unroll
        for (int ip = 0; ip < 4; ip++)
            #pragma unroll
            for (int jj = 0; jj < 8; jj++) s2[ip][jj] = 0ull;

        #pragma unroll 4
        for (int d = 0; d < HD; d++) {
            ull a2[4];
            #pragma unroll
            for (int ip = 0; ip < 4; ip++)
                a2[ip] = lds64(sb + 4u * (d * AP_K + ty * 8 + 2 * ip));
            ull bd[8];
            #pragma unroll
            for (int jj = 0; jj < 8; jj++) {
                float bq = sm[OQ_ + (tx + 16*jj) * AP_Q + d];
                bd[jj] = pk2(bq, bq);
            }
            #pragma unroll
            for (int ip = 0; ip < 4; ip++)
                #pragma unroll
                for (int jj = 0; jj < 8; jj++)
                    fma2(s2[ip][jj], a2[ip], bd[jj]);
        }

        // ---- online softmax (per row) + P store ----
        #pragma unroll
        for (int ip = 0; ip < 4; ip++) {
            float sl[8], sh[8];
            #pragma unroll
            for (int jj = 0; jj < 8; jj++) upk2(s2[ip][jj], sl[jj], sh[jj]);

            float mx0 = sl[0], mx1 = sh[0];
            #pragma unroll
            for (int jj = 1; jj < 8; jj++) {
                mx0 = fmaxf(mx0, sl[jj]);
                mx1 = fmaxf(mx1, sh[jj]);
            }
            #pragma unroll
            for (int off = 8; off > 0; off >>= 1) {
                mx0 = fmaxf(mx0, __shfl_xor_sync(0xffffffffu, mx0, off));
                mx1 = fmaxf(mx1, __shfl_xor_sync(0xffffffffu, mx1, off));
            }
            const float mn0 = fmaxf(m[2*ip],   mx0);
            const float mn1 = fmaxf(m[2*ip+1], mx1);
            const float al0 = __expf(m[2*ip]   - mn0);
            const float al1 = __expf(m[2*ip+1] - mn1);
            float rs0 = 0.f, rs1 = 0.f;
            #pragma unroll
            for (int jj = 0; jj < 8; jj++) {
                sl[jj] = __expf(sl[jj] - mn0); rs0 += sl[jj];
                sh[jj] = __expf(sh[jj] - mn1); rs1 += sh[jj];
            }
            #pragma unroll
            for (int off = 8; off > 0; off >>= 1) {
                rs0 += __shfl_xor_sync(0xffffffffu, rs0, off);
                rs1 += __shfl_xor_sync(0xffffffffu, rs1, off);
            }
            lsum[2*ip]   = lsum[2*ip]   * al0 + rs0;  m[2*ip]   = mn0;
            lsum[2*ip+1] = lsum[2*ip+1] * al1 + rs1;  m[2*ip+1] = mn1;
            const ull alp = pk2(al0, al1);
            #pragma unroll
            for (int c = 0; c < 4; c++) mul2(o2[ip][c], alp);
            #pragma unroll
            for (int jj = 0; jj < 8; jj++)
                sts64(sb + 4u * (OP_ + (tx + 16*jj) * AP_P + ty * 8 + 2 * ip),
                      pk2(sl[jj], sh[jj]));
        }
        __syncthreads();

        // ---- O += P @ V ----
        #pragma unroll 2
        for (int j = 0; j < BJ; j++) {
            ull p2[4];
            #pragma unroll
            for (int ip = 0; ip < 4; ip++)
                p2[ip] = lds64(sb + 4u * (OP_ + j * AP_P + ty * 8 + 2 * ip));
            float4 vv = *reinterpret_cast<const float4*>(&sm[OV_ + j * AP_V + tx * 4]);
            ull v2[4];
            v2[0] = pk2(vv.x, vv.x); v2[1] = pk2(vv.y, vv.y);
            v2[2] = pk2(vv.z, vv.z); v2[3] = pk2(vv.w, vv.w);
            #pragma unroll
            for (int ip = 0; ip < 4; ip++)
                #pragma unroll
                for (int c = 0; c < 4; c++)
                    fma2(o2[ip][c], p2[ip], v2[c]);
        }
        __syncthreads();
    }

    // ---- normalize + store ----
    #pragma unroll
    for (int ip = 0; ip < 4; ip++) {
        float x0,x1,y0,y1,z0,z1,w0,w1;
        upk2(o2[ip][0], x0, x1);
        upk2(o2[ip][1], y0, y1);
        upk2(o2[ip][2], z0, z1);
        upk2(o2[ip][3], w0, w1);
        const float iv0 = 1.0f / lsum[2*ip];
        const float iv1 = 1.0f / lsum[2*ip+1];
        const int r0 = i0 + ty * 8 + 2 * ip;
        *reinterpret_cast<float4*>(&O[base + (size_t)r0 * D_ + tx * 4]) =
            make_float4(x0*iv0, y0*iv0, z0*iv0, w0*iv0);
        *reinterpret_cast<float4*>(&O[base + (size_t)(r0+1) * D_ + tx * 4]) =
            make_float4(x1*iv1, y1*iv1, z1*iv1, w1*iv1);
    }
}

// ---------------------------------------------------------------------------
extern "C" void kernel_launch(void* const* d_in, const int* in_sizes, int n_in,
                              void* d_out, int out_size)
{
    const float* seq_k = (const float*)d_in[0];
    const float* seq_q = (const float*)d_in[1];
    const float* seq_v = (const float*)d_in[2];
    const float* W1    = (const float*)d_in[3];
    const float* W2    = (const float*)d_in[4];
    const float* W3    = (const float*)d_in[5];
    const float* gamma = (const float*)d_in[6];
    const float* beta  = (const float*)d_in[7];
    float* out = (float*)d_out;

    float *vin, *q, *k, *v, *att;
    cudaGetSymbolAddress((void**)&vin, g_vin);
    cudaGetSymbolAddress((void**)&q,   g_q);
    cudaGetSymbolAddress((void**)&k,   g_k);
    cudaGetSymbolAddress((void**)&v,   g_v);
    cudaGetSymbolAddress((void**)&att, g_att);

    // 1) v_in = LN(seq_v)
    ln_kernel<<<M_, 128>>>(seq_v, nullptr, gamma, beta, vin);

    // 2) q = seq_q @ W1^T ; k = seq_k @ W2^T ; v = v_in @ W3^T
    dim3 ggrid(D_ / BN, M_ / BM);
    gemm_nt<<<ggrid, 256>>>(seq_q, W1, q);
    gemm_nt<<<ggrid, 256>>>(seq_k, W2, k);
    gemm_nt<<<ggrid, 256>>>(vin,   W3, v);

    // 3) attention
    cudaFuncSetAttribute(attn_kernel, cudaFuncAttributeMaxDynamicSharedMemorySize, ATTN_SMEM);
    attn_kernel<<<dim3(S_ / BI, B_ * H_), 256, ATTN_SMEM>>>(q, k, v, att);

    // 4) out = LN(att + v_in)
    ln_kernel<<<M_, 128>>>(att, vin, gamma, beta, out);
}

// round 4
// speedup vs baseline: 3.4149x; 2.2290x over previous
#include <cuda_runtime.h>
#include <cuda_bf16.h>
#include <math.h>

#define B_ 4
#define S_ 2048
#define D_ 512
#define H_ 8
#define HD 64
#define M_ (B_*S_)
#define EPS_ 1e-5f

typedef unsigned long long ull;

// ---------------------------------------------------------------------------
// Scratch (__device__ globals; allocation-free rule)
// ---------------------------------------------------------------------------
__device__ float g_vin[(size_t)M_*D_];
__device__ float g_att[(size_t)M_*D_];
// split inputs (hi/lo bf16 packed as ull quads)
__device__ ull g_sqh[M_*D_/4], g_sql[M_*D_/4];
__device__ ull g_skh[M_*D_/4], g_skl[M_*D_/4];
__device__ ull g_svh[M_*D_/4], g_svl[M_*D_/4];
__device__ ull g_w1h[D_*D_/4], g_w1l[D_*D_/4];
__device__ ull g_w2h[D_*D_/4], g_w2l[D_*D_/4];
__device__ ull g_w3h[D_*D_/4], g_w3l[D_*D_/4];
// projection outputs (hi/lo bf16)
__device__ ull g_qh[M_*D_/4], g_ql[M_*D_/4];
__device__ ull g_kh[M_*D_/4], g_kl[M_*D_/4];
__device__ ull g_vh[M_*D_/4], g_vl[M_*D_/4];

// ---------------------------------------------------------------------------
// helpers
// ---------------------------------------------------------------------------
__device__ __forceinline__ unsigned smem_u32(const void* p) {
    unsigned r;
    asm("{ .reg .u64 t; cvta.to.shared.u64 t, %1; cvt.u32.u64 %0, t; }"
        : "=r"(r) : "l"(p));
    return r;
}

// split two fp32 into packed-hi bf16x2 and packed-lo bf16x2 ({x lo16, y hi16})
__device__ __forceinline__ void splitpk(float x, float y, unsigned& hp, unsigned& lp) {
    __nv_bfloat16 hx = __float2bfloat16(x), hy = __float2bfloat16(y);
    float rx = x - __bfloat162float(hx), ry = y - __bfloat162float(hy);
    __nv_bfloat16 lx = __float2bfloat16(rx), ly = __float2bfloat16(ry);
    hp = ((unsigned)__bfloat16_as_ushort(hy) << 16) | (unsigned)__bfloat16_as_ushort(hx);
    lp = ((unsigned)__bfloat16_as_ushort(ly) << 16) | (unsigned)__bfloat16_as_ushort(lx);
}

#define MMA_BF16(c, a, b0, b1) \
    asm volatile("mma.sync.aligned.m16n8k16.row.col.f32.bf16.bf16.f32 " \
        "{%0,%1,%2,%3}, {%4,%5,%6,%7}, {%8,%9}, {%0,%1,%2,%3};" \
        : "+f"((c)[0]), "+f"((c)[1]), "+f"((c)[2]), "+f"((c)[3]) \
        : "r"((a)[0]), "r"((a)[1]), "r"((a)[2]), "r"((a)[3]), "r"(b0), "r"(b1))

#define LDSM4(r0,r1,r2,r3,addr) \
    asm volatile("ldmatrix.sync.aligned.m8n8.x4.shared.b16 {%0,%1,%2,%3}, [%4];" \
        : "=r"(r0),"=r"(r1),"=r"(r2),"=r"(r3) : "r"(addr))
#define LDSM4T(r0,r1,r2,r3,addr) \
    asm volatile("ldmatrix.sync.aligned.m8n8.x4.trans.shared.b16 {%0,%1,%2,%3}, [%4];" \
        : "=r"(r0),"=r"(r1),"=r"(r2),"=r"(r3) : "r"(addr))

// row stride of bf16 tiles in smem: 64 elems + 8 pad = 144 bytes (LDSM conflict-free)
#define TSB 144

// ---------------------------------------------------------------------------
// split kernel: fp32 -> (hi, lo) bf16 arrays, 4 elems/thread
// ---------------------------------------------------------------------------
__global__ __launch_bounds__(256) void split_kernel(
    const float4* __restrict__ x, ull* __restrict__ hi, ull* __restrict__ lo, int n4)
{
    int i = blockIdx.x * 256 + threadIdx.x;
    if (i >= n4) return;
    float4 v = x[i];
    unsigned h01, l01, h23, l23;
    splitpk(v.x, v.y, h01, l01);
    splitpk(v.z, v.w, h23, l23);
    hi[i] = ((ull)h23 << 32) | h01;
    lo[i] = ((ull)l23 << 32) | l01;
}

// ---------------------------------------------------------------------------
// LayerNorm (unchanged)
// ---------------------------------------------------------------------------
__global__ __launch_bounds__(128) void ln_kernel(
    const float* __restrict__ x, const float* __restrict__ res,
    const float* __restrict__ gamma, const float* __restrict__ beta,
    float* __restrict__ y)
{
    const int row = blockIdx.x;
    const int tid = threadIdx.x;
    const float4* x4 = reinterpret_cast<const float4*>(x + (size_t)row * D_);
    float4 v = x4[tid];
    if (res) {
        const float4* r4 = reinterpret_cast<const float4*>(res + (size_t)row * D_);
        float4 r = r4[tid];
        v.x += r.x; v.y += r.y; v.z += r.z; v.w += r.w;
    }
    float s  = v.x + v.y + v.z + v.w;
    float ss = v.x*v.x + v.y*v.y + v.z*v.z + v.w*v.w;
    #pragma unroll
    for (int o = 16; o > 0; o >>= 1) {
        s  += __shfl_xor_sync(0xffffffffu, s,  o);
        ss += __shfl_xor_sync(0xffffffffu, ss, o);
    }
    __shared__ float sb[4], ssb[4];
    const int w = tid >> 5;
    if ((tid & 31) == 0) { sb[w] = s; ssb[w] = ss; }
    __syncthreads();
    s  = sb[0]  + sb[1]  + sb[2]  + sb[3];
    ss = ssb[0] + ssb[1] + ssb[2] + ssb[3];
    const float mu   = s * (1.0f / D_);
    const float var  = ss * (1.0f / D_) - mu * mu;
    const float rstd = rsqrtf(var + EPS_);
    const float4 g = reinterpret_cast<const float4*>(gamma)[tid];
    const float4 b = reinterpret_cast<const float4*>(beta )[tid];
    float4 o;
    o.x = (v.x - mu) * rstd * g.x + b.x;
    o.y = (v.y - mu) * rstd * g.y + b.y;
    o.z = (v.z - mu) * rstd * g.z + b.z;
    o.w = (v.w - mu) * rstd * g.w + b.w;
    reinterpret_cast<float4*>(y + (size_t)row * D_)[tid] = o;
}

// ---------------------------------------------------------------------------
// HMMA NT GEMM (bf16 split): C[m,n] = sum_k A[m,k]*W[n,k]. 128x128 CTA,
// 8 warps each m16 x n128; K in 8 smem chunks of 64. Epilogue emits bf16 hi/lo.
// ---------------------------------------------------------------------------
#define GOAH 0
#define GOAL (128*TSB)
#define GOWH (2*128*TSB)
#define GOWL (3*128*TSB)
#define GEMM_SMEM (4*128*TSB)     // 73728 B

__global__ __launch_bounds__(256) void gemm_tc(
    const ull* __restrict__ Ah, const ull* __restrict__ Al,
    const ull* __restrict__ Wh, const ull* __restrict__ Wl,
    __nv_bfloat16* __restrict__ Ch, __nv_bfloat16* __restrict__ Cl)
{
    extern __shared__ char smc[];
    const unsigned sbase = smem_u32(smc);
    const int tid = threadIdx.x;
    const int lane = tid & 31;
    const int w = tid >> 5;
    const int m0 = blockIdx.y * 128;
    const int n0 = blockIdx.x * 128;

    float Ca[16][4];
    #pragma unroll
    for (int nb = 0; nb < 16; nb++)
        #pragma unroll
        for (int r = 0; r < 4; r++) Ca[nb][r] = 0.f;

    const unsigned a_off = (unsigned)((lane & 15) * TSB + (lane >> 4) * 16) + (unsigned)(w * 16 * TSB);
    const unsigned b_off = (unsigned)((((lane >> 4) * 8) + (lane & 7)) * TSB + ((lane >> 3) & 1) * 16);

    for (int c = 0; c < 8; c++) {
        #pragma unroll
        for (int l = 0; l < 8; l++) {
            const int idx = tid + l * 256;
            const int r  = idx >> 4;
            const int cq = idx & 15;
            const size_t ga = (size_t)(m0 + r) * 128 + c * 16 + cq;
            const size_t gw = (size_t)(n0 + r) * 128 + c * 16 + cq;
            *(ull*)(smc + GOAH + r*TSB + cq*8) = Ah[ga];
            *(ull*)(smc + GOAL + r*TSB + cq*8) = Al[ga];
            *(ull*)(smc + GOWH + r*TSB + cq*8) = Wh[gw];
            *(ull*)(smc + GOWL + r*TSB + cq*8) = Wl[gw];
        }
        __syncthreads();

        unsigned aha[4][4], ala[4][4];
        #pragma unroll
        for (int ks = 0; ks < 4; ks++) {
            LDSM4(aha[ks][0], aha[ks][1], aha[ks][2], aha[ks][3], sbase + GOAH + a_off + ks*32);
            LDSM4(ala[ks][0], ala[ks][1], ala[ks][2], ala[ks][3], sbase + GOAL + a_off + ks*32);
        }
        #pragma unroll
        for (int jbp = 0; jbp < 8; jbp++) {
            #pragma unroll
            for (int ks = 0; ks < 4; ks++) {
                unsigned bh0,bh1,bh2,bh3, bl0,bl1,bl2,bl3;
                LDSM4(bh0,bh1,bh2,bh3, sbase + GOWH + (unsigned)(jbp*16*TSB) + ks*32 + b_off);
                LDSM4(bl0,bl1,bl2,bl3, sbase + GOWL + (unsigned)(jbp*16*TSB) + ks*32 + b_off);
                MMA_BF16(Ca[2*jbp],   aha[ks], bh0, bh1);
                MMA_BF16(Ca[2*jbp],   aha[ks], bl0, bl1);
                MMA_BF16(Ca[2*jbp],   ala[ks], bh0, bh1);
                MMA_BF16(Ca[2*jbp+1], aha[ks], bh2, bh3);
                MMA_BF16(Ca[2*jbp+1], aha[ks], bl2, bl3);
                MMA_BF16(Ca[2*jbp+1], ala[ks], bh2, bh3);
            }
        }
        __syncthreads();
    }

    const int g = lane >> 2, t = lane & 3;
    const int r0 = m0 + w * 16 + g;
    const int r1 = r0 + 8;
    #pragma unroll
    for (int nb = 0; nb < 16; nb++) {
        const int col = n0 + nb * 8 + 2 * t;
        unsigned h01, l01, h23, l23;
        splitpk(Ca[nb][0], Ca[nb][1], h01, l01);
        splitpk(Ca[nb][2], Ca[nb][3], h23, l23);
        *(unsigned*)&Ch[(size_t)r0 * D_ + col] = h01;
        *(unsigned*)&Cl[(size_t)r0 * D_ + col] = l01;
        *(unsigned*)&Ch[(size_t)r1 * D_ + col] = h23;
        *(unsigned*)&Cl[(size_t)r1 * D_ + col] = l23;
    }
}

// ---------------------------------------------------------------------------
// HMMA attention. scores[i,j] = dot(K_i, Q_j); softmax over j; O = P @ V.
// Block = (128 i-rows, bh). 8 warps, warp = 16 i-rows x full 128-j tile.
// K fragments persist in registers; P stays in registers (C-frag -> A-frag).
// ---------------------------------------------------------------------------
#define AOKH 0
#define AOKL (128*TSB)
#define AOQH (2*128*TSB)
#define AOQL (3*128*TSB)
#define AOVH (4*128*TSB)
#define AOVL (5*128*TSB)
#define ATTN_SMEM (6*128*TSB)     // 110592 B

__global__ __launch_bounds__(256, 1) void attn_tc(
    const ull* __restrict__ Qh, const ull* __restrict__ Ql,
    const ull* __restrict__ Kh, const ull* __restrict__ Kl,
    const ull* __restrict__ Vh, const ull* __restrict__ Vl,
    float* __restrict__ O)
{
    extern __shared__ char smc[];
    const unsigned sbase = smem_u32(smc);
    const int tid = threadIdx.x;
    const int lane = tid & 31;
    const int w = tid >> 5;
    const int it = blockIdx.x;
    const int bh = blockIdx.y;
    const int b = bh >> 3, h = bh & 7;
    const size_t base = (size_t)b * S_ * D_ + (size_t)h * HD;
    const size_t base4 = base >> 2;
    const int i0 = it * 128;

    // load K tile (128 x 64, hi/lo)
    #pragma unroll
    for (int l = 0; l < 8; l++) {
        const int idx = tid + l * 256;
        const int r  = idx >> 4;
        const int cq = idx & 15;
        const size_t gk = base4 + (size_t)(i0 + r) * 128 + cq;
        *(ull*)(smc + AOKH + r*TSB + cq*8) = Kh[gk];
        *(ull*)(smc + AOKL + r*TSB + cq*8) = Kl[gk];
    }
    __syncthreads();

    // persistent K fragments (A operand): m16 x k64
    const unsigned a_off = (unsigned)((lane & 15) * TSB + (lane >> 4) * 16) + (unsigned)(w * 16 * TSB);
    unsigned kha[4][4], kla[4][4];
    #pragma unroll
    for (int ks = 0; ks < 4; ks++) {
        LDSM4(kha[ks][0], kha[ks][1], kha[ks][2], kha[ks][3], sbase + AOKH + a_off + ks*32);
        LDSM4(kla[ks][0], kla[ks][1], kla[ks][2], kla[ks][3], sbase + AOKL + a_off + ks*32);
    }

    const unsigned b_off = (unsigned)((((lane >> 4) * 8) + (lane & 7)) * TSB + ((lane >> 3) & 1) * 16);
    const unsigned v_off = (unsigned)(((((lane >> 3) & 1) * 8) + (lane & 7)) * TSB + (lane >> 4) * 16);

    float Oa[8][4];
    #pragma unroll
    for (int db = 0; db < 8; db++)
        #pragma unroll
        for (int r = 0; r < 4; r++) Oa[db][r] = 0.f;
    float m0 = -1e30f, m1 = -1e30f, lsum0 = 0.f, lsum1 = 0.f;

    for (int jt = 0; jt < 16; jt++) {
        const int j0 = jt * 128;
        // load Q, V tiles (hi/lo)
        #pragma unroll
        for (int l = 0; l < 8; l++) {
            const int idx = tid + l * 256;
            const int r  = idx >> 4;
            const int cq = idx & 15;
            const size_t gq = base4 + (size_t)(j0 + r) * 128 + cq;
            *(ull*)(smc + AOQH + r*TSB + cq*8) = Qh[gq];
            *(ull*)(smc + AOQL + r*TSB + cq*8) = Ql[gq];
            *(ull*)(smc + AOVH + r*TSB + cq*8) = Vh[gq];
            *(ull*)(smc + AOVL + r*TSB + cq*8) = Vl[gq];
        }
        __syncthreads();

        // ---- S = K @ Q^T : warp rows 16, cols 128 (16 nblocks) ----
        float Sa[16][4];
        #pragma unroll
        for (int nb = 0; nb < 16; nb++)
            #pragma unroll
            for (int r = 0; r < 4; r++) Sa[nb][r] = 0.f;

        #pragma unroll
        for (int jbp = 0; jbp < 8; jbp++) {
            #pragma unroll
            for (int ks = 0; ks < 4; ks++) {
                unsigned bh0,bh1,bh2,bh3, bl0,bl1,bl2,bl3;
                LDSM4(bh0,bh1,bh2,bh3, sbase + AOQH + (unsigned)(jbp*16*TSB) + ks*32 + b_off);
                LDSM4(bl0,bl1,bl2,bl3, sbase + AOQL + (unsigned)(jbp*16*TSB) + ks*32 + b_off);
                MMA_BF16(Sa[2*jbp],   kha[ks], bh0, bh1);
                MMA_BF16(Sa[2*jbp],   kha[ks], bl0, bl1);
                MMA_BF16(Sa[2*jbp],   kla[ks], bh0, bh1);
                MMA_BF16(Sa[2*jbp+1], kha[ks], bh2, bh3);
                MMA_BF16(Sa[2*jbp+1], kha[ks], bl2, bl3);
                MMA_BF16(Sa[2*jbp+1], kla[ks], bh2, bh3);
            }
        }

        // ---- online softmax: lane owns rows g (c0,c1) and g+8 (c2,c3) ----
        float mx0 = -1e30f, mx1 = -1e30f;
        #pragma unroll
        for (int nb = 0; nb < 16; nb++) {
            mx0 = fmaxf(mx0, fmaxf(Sa[nb][0], Sa[nb][1]));
            mx1 = fmaxf(mx1, fmaxf(Sa[nb][2], Sa[nb][3]));
        }
        mx0 = fmaxf(mx0, __shfl_xor_sync(0xffffffffu, mx0, 1));
        mx0 = fmaxf(mx0, __shfl_xor_sync(0xffffffffu, mx0, 2));
        mx1 = fmaxf(mx1, __shfl_xor_sync(0xffffffffu, mx1, 1));
        mx1 = fmaxf(mx1, __shfl_xor_sync(0xffffffffu, mx1, 2));
        const float mn0 = fmaxf(m0, mx0);
        const float mn1 = fmaxf(m1, mx1);
        const float al0 = __expf(m0 - mn0);
        const float al1 = __expf(m1 - mn1);
        float rs0 = 0.f, rs1 = 0.f;
        #pragma unroll
        for (int nb = 0; nb < 16; nb++) {
            Sa[nb][0] = __expf(Sa[nb][0] - mn0);
            Sa[nb][1] = __expf(Sa[nb][1] - mn0);
            Sa[nb][2] = __expf(Sa[nb][2] - mn1);
            Sa[nb][3] = __expf(Sa[nb][3] - mn1);
            rs0 += Sa[nb][0] + Sa[nb][1];
            rs1 += Sa[nb][2] + Sa[nb][3];
        }
        rs0 += __shfl_xor_sync(0xffffffffu, rs0, 1);
        rs0 += __shfl_xor_sync(0xffffffffu, rs0, 2);
        rs1 += __shfl_xor_sync(0xffffffffu, rs1, 1);
        rs1 += __shfl_xor_sync(0xffffffffu, rs1, 2);
        lsum0 = lsum0 * al0 + rs0;  m0 = mn0;
        lsum1 = lsum1 * al1 + rs1;  m1 = mn1;
        #pragma unroll
        for (int db = 0; db < 8; db++) {
            Oa[db][0] *= al0; Oa[db][1] *= al0;
            Oa[db][2] *= al1; Oa[db][3] *= al1;
        }

        // ---- O += P @ V : P from registers (C-frag -> A-frag), V via ldsm.trans
        #pragma unroll
        for (int ks = 0; ks < 8; ks++) {
            unsigned pah[4], pal[4];
            splitpk(Sa[2*ks][0],   Sa[2*ks][1],   pah[0], pal[0]);
            splitpk(Sa[2*ks][2],   Sa[2*ks][3],   pah[1], pal[1]);
            splitpk(Sa[2*ks+1][0], Sa[2*ks+1][1], pah[2], pal[2]);
            splitpk(Sa[2*ks+1][2], Sa[2*ks+1][3], pah[3], pal[3]);
            #pragma unroll
            for (int dbp = 0; dbp < 4; dbp++) {
                unsigned vh0,vh1,vh2,vh3, vl0,vl1,vl2,vl3;
                LDSM4T(vh0,vh1,vh2,vh3, sbase + AOVH + (unsigned)(ks*16*TSB) + dbp*32 + v_off);
                LDSM4T(vl0,vl1,vl2,vl3, sbase + AOVL + (unsigned)(ks*16*TSB) + dbp*32 + v_off);
                MMA_BF16(Oa[2*dbp],   pah, vh0, vh1);
                MMA_BF16(Oa[2*dbp],   pah, vl0, vl1);
                MMA_BF16(Oa[2*dbp],   pal, vh0, vh1);
                MMA_BF16(Oa[2*dbp+1], pah, vh2, vh3);
                MMA_BF16(Oa[2*dbp+1], pah, vl2, vl3);
                MMA_BF16(Oa[2*dbp+1], pal, vh2, vh3);
            }
        }
        __syncthreads();
    }

    // ---- normalize + write ----
    const float inv0 = 1.0f / lsum0;
    const float inv1 = 1.0f / lsum1;
    const int g = lane >> 2, t = lane & 3;
    const int r0 = i0 + w * 16 + g;
    const int r1 = r0 + 8;
    #pragma unroll
    for (int db = 0; db < 8; db++) {
        const int col = db * 8 + 2 * t;
        *(float2*)&O[base + (size_t)r0 * D_ + col] = make_float2(Oa[db][0]*inv0, Oa[db][1]*inv0);
        *(float2*)&O[base + (size_t)r1 * D_ + col] = make_float2(Oa[db][2]*inv1, Oa[db][3]*inv1);
    }
}

// ---------------------------------------------------------------------------
extern "C" void kernel_launch(void* const* d_in, const int* in_sizes, int n_in,
                              void* d_out, int out_size)
{
    const float* seq_k = (const float*)d_in[0];
    const float* seq_q = (const float*)d_in[1];
    const float* seq_v = (const float*)d_in[2];
    const float* W1    = (const float*)d_in[3];
    const float* W2    = (const float*)d_in[4];
    const float* W3    = (const float*)d_in[5];
    const float* gamma = (const float*)d_in[6];
    const float* beta  = (const float*)d_in[7];
    float* out = (float*)d_out;

    float *vin, *att;
    ull *sqh,*sql,*skh,*skl,*svh,*svl,*w1h,*w1l,*w2h,*w2l,*w3h,*w3l;
    ull *qh,*ql,*kh,*kl,*vh,*vl;
    cudaGetSymbolAddress((void**)&vin, g_vin);
    cudaGetSymbolAddress((void**)&att, g_att);
    cudaGetSymbolAddress((void**)&sqh, g_sqh); cudaGetSymbolAddress((void**)&sql, g_sql);
    cudaGetSymbolAddress((void**)&skh, g_skh); cudaGetSymbolAddress((void**)&skl, g_skl);
    cudaGetSymbolAddress((void**)&svh, g_svh); cudaGetSymbolAddress((void**)&svl, g_svl);
    cudaGetSymbolAddress((void**)&w1h, g_w1h); cudaGetSymbolAddress((void**)&w1l, g_w1l);
    cudaGetSymbolAddress((void**)&w2h, g_w2h); cudaGetSymbolAddress((void**)&w2l, g_w2l);
    cudaGetSymbolAddress((void**)&w3h, g_w3h); cudaGetSymbolAddress((void**)&w3l, g_w3l);
    cudaGetSymbolAddress((void**)&qh,  g_qh);  cudaGetSymbolAddress((void**)&ql,  g_ql);
    cudaGetSymbolAddress((void**)&kh,  g_kh);  cudaGetSymbolAddress((void**)&kl,  g_kl);
    cudaGetSymbolAddress((void**)&vh,  g_vh);  cudaGetSymbolAddress((void**)&vl,  g_vl);

    // 1) v_in = LN(seq_v)
    ln_kernel<<<M_, 128>>>(seq_v, nullptr, gamma, beta, vin);

    // 2) split inputs + weights to bf16 hi/lo
    const int n4i = M_ * D_ / 4;   // 1048576
    const int n4w = D_ * D_ / 4;   // 65536
    split_kernel<<<n4i/256, 256>>>((const float4*)seq_q, sqh, sql, n4i);
    split_kernel<<<n4i/256, 256>>>((const float4*)seq_k, skh, skl, n4i);
    split_kernel<<<n4i/256, 256>>>((const float4*)vin,   svh, svl, n4i);
    split_kernel<<<n4w/256, 256>>>((const float4*)W1,    w1h, w1l, n4w);
    split_kernel<<<n4w/256, 256>>>((const float4*)W2,    w2h, w2l, n4w);
    split_kernel<<<n4w/256, 256>>>((const float4*)W3,    w3h, w3l, n4w);

    // 3) projections on HMMA (outputs split bf16)
    cudaFuncSetAttribute(gemm_tc, cudaFuncAttributeMaxDynamicSharedMemorySize, GEMM_SMEM);
    dim3 ggrid(D_ / 128, M_ / 128);
    gemm_tc<<<ggrid, 256, GEMM_SMEM>>>(sqh, sql, w1h, w1l, (__nv_bfloat16*)qh, (__nv_bfloat16*)ql);
    gemm_tc<<<ggrid, 256, GEMM_SMEM>>>(skh, skl, w2h, w2l, (__nv_bfloat16*)kh, (__nv_bfloat16*)kl);
    gemm_tc<<<ggrid, 256, GEMM_SMEM>>>(svh, svl, w3h, w3l, (__nv_bfloat16*)vh, (__nv_bfloat16*)vl);

    // 4) attention on HMMA
    cudaFuncSetAttribute(attn_tc, cudaFuncAttributeMaxDynamicSharedMemorySize, ATTN_SMEM);
    attn_tc<<<dim3(S_ / 128, B_ * H_), 256, ATTN_SMEM>>>(qh, ql, kh, kl, vh, vl, att);

    // 5) out = LN(att + v_in)
    ln_kernel<<<M_, 128>>>(att, vin, gamma, beta, out);
}

// round 5
// speedup vs baseline: 3.8292x; 1.1213x over previous
#include <cuda_runtime.h>
#include <cuda_bf16.h>
#include <math.h>

#define B_ 4
#define S_ 2048
#define D_ 512
#define H_ 8
#define HD 64
#define M_ (B_*S_)
#define EPS_ 1e-5f

typedef unsigned long long ull;

// ---------------------------------------------------------------------------
// Scratch (__device__ globals; allocation-free rule)
// ---------------------------------------------------------------------------
__device__ float g_vin[(size_t)M_*D_];
__device__ float g_att[(size_t)M_*D_];
__device__ ull g_sqh[M_*D_/4], g_sql[M_*D_/4];
__device__ ull g_skh[M_*D_/4], g_skl[M_*D_/4];
__device__ ull g_svh[M_*D_/4], g_svl[M_*D_/4];
__device__ ull g_w1h[D_*D_/4], g_w1l[D_*D_/4];
__device__ ull g_w2h[D_*D_/4], g_w2l[D_*D_/4];
__device__ ull g_w3h[D_*D_/4], g_w3l[D_*D_/4];
__device__ ull g_qh[M_*D_/4], g_ql[M_*D_/4];
__device__ ull g_kh[M_*D_/4], g_kl[M_*D_/4];
__device__ ull g_vh[M_*D_/4], g_vl[M_*D_/4];

// ---------------------------------------------------------------------------
// helpers
// ---------------------------------------------------------------------------
__device__ __forceinline__ unsigned smem_u32(const void* p) {
    unsigned r;
    asm("{ .reg .u64 t; cvta.to.shared.u64 t, %1; cvt.u32.u64 %0, t; }"
        : "=r"(r) : "l"(p));
    return r;
}
__device__ __forceinline__ void splitpk(float x, float y, unsigned& hp, unsigned& lp) {
    __nv_bfloat16 hx = __float2bfloat16(x), hy = __float2bfloat16(y);
    float rx = x - __bfloat162float(hx), ry = y - __bfloat162float(hy);
    __nv_bfloat16 lx = __float2bfloat16(rx), ly = __float2bfloat16(ry);
    hp = ((unsigned)__bfloat16_as_ushort(hy) << 16) | (unsigned)__bfloat16_as_ushort(hx);
    lp = ((unsigned)__bfloat16_as_ushort(ly) << 16) | (unsigned)__bfloat16_as_ushort(lx);
}

#define MMA_BF16(c, a, b0, b1) \
    asm volatile("mma.sync.aligned.m16n8k16.row.col.f32.bf16.bf16.f32 " \
        "{%0,%1,%2,%3}, {%4,%5,%6,%7}, {%8,%9}, {%0,%1,%2,%3};" \
        : "+f"((c)[0]), "+f"((c)[1]), "+f"((c)[2]), "+f"((c)[3]) \
        : "r"((a)[0]), "r"((a)[1]), "r"((a)[2]), "r"((a)[3]), "r"(b0), "r"(b1))

#define LDSM4(r0,r1,r2,r3,addr) \
    asm volatile("ldmatrix.sync.aligned.m8n8.x4.shared.b16 {%0,%1,%2,%3}, [%4];" \
        : "=r"(r0),"=r"(r1),"=r"(r2),"=r"(r3) : "r"(addr))
#define LDSM4T(r0,r1,r2,r3,addr) \
    asm volatile("ldmatrix.sync.aligned.m8n8.x4.trans.shared.b16 {%0,%1,%2,%3}, [%4];" \
        : "=r"(r0),"=r"(r1),"=r"(r2),"=r"(r3) : "r"(addr))

__device__ __forceinline__ void cpa16(unsigned sa, const void* ga) {
    asm volatile("cp.async.cg.shared.global [%0], [%1], 16;" :: "r"(sa), "l"(ga) : "memory");
}
#define CPA_COMMIT() asm volatile("cp.async.commit_group;" ::: "memory")
#define CPA_WAIT(n)  asm volatile("cp.async.wait_group %0;" :: "n"(n) : "memory")

// bf16 tile row stride: 64 elems (128B data) + 16B pad = 144 B (LDSM conflict-free)
#define TSB 144
#define TS  (128*TSB)   // 18432 B per 128x64 tile

// async-copy one 128x64 bf16 tile (16 ull/row in gmem) into padded smem
__device__ __forceinline__ void cpa_tile(unsigned dst, const ull* __restrict__ src,
                                         size_t rowbase, int tid) {
    #pragma unroll
    for (int l = 0; l < 4; l++) {
        const int idx = tid + l * 256;       // 0..1023
        const int r = idx >> 3, c8 = idx & 7;
        cpa16(dst + (unsigned)(r * TSB + c8 * 16), src + rowbase + (size_t)r * 128 + c8 * 2);
    }
}

// ---------------------------------------------------------------------------
// split kernel: fp32 -> (hi, lo) bf16 arrays
// ---------------------------------------------------------------------------
__global__ __launch_bounds__(256) void split_kernel(
    const float4* __restrict__ x, ull* __restrict__ hi, ull* __restrict__ lo, int n4)
{
    int i = blockIdx.x * 256 + threadIdx.x;
    if (i >= n4) return;
    float4 v = x[i];
    unsigned h01, l01, h23, l23;
    splitpk(v.x, v.y, h01, l01);
    splitpk(v.z, v.w, h23, l23);
    hi[i] = ((ull)h23 << 32) | h01;
    lo[i] = ((ull)l23 << 32) | l01;
}

// ---------------------------------------------------------------------------
// LayerNorm; optionally also emits split bf16 hi/lo of the result.
// ---------------------------------------------------------------------------
__global__ __launch_bounds__(128) void ln_kernel(
    const float* __restrict__ x, const float* __restrict__ res,
    const float* __restrict__ gamma, const float* __restrict__ beta,
    float* __restrict__ y, ull* __restrict__ yh, ull* __restrict__ yl)
{
    const int row = blockIdx.x;
    const int tid = threadIdx.x;
    const float4* x4 = reinterpret_cast<const float4*>(x + (size_t)row * D_);
    float4 v = x4[tid];
    if (res) {
        const float4* r4 = reinterpret_cast<const float4*>(res + (size_t)row * D_);
        float4 r = r4[tid];
        v.x += r.x; v.y += r.y; v.z += r.z; v.w += r.w;
    }
    float s  = v.x + v.y + v.z + v.w;
    float ss = v.x*v.x + v.y*v.y + v.z*v.z + v.w*v.w;
    #pragma unroll
    for (int o = 16; o > 0; o >>= 1) {
        s  += __shfl_xor_sync(0xffffffffu, s,  o);
        ss += __shfl_xor_sync(0xffffffffu, ss, o);
    }
    __shared__ float sb[4], ssb[4];
    const int w = tid >> 5;
    if ((tid & 31) == 0) { sb[w] = s; ssb[w] = ss; }
    __syncthreads();
    s  = sb[0]  + sb[1]  + sb[2]  + sb[3];
    ss = ssb[0] + ssb[1] + ssb[2] + ssb[3];
    const float mu   = s * (1.0f / D_);
    const float var  = ss * (1.0f / D_) - mu * mu;
    const float rstd = rsqrtf(var + EPS_);
    const float4 g = reinterpret_cast<const float4*>(gamma)[tid];
    const float4 b = reinterpret_cast<const float4*>(beta )[tid];
    float4 o;
    o.x = (v.x - mu) * rstd * g.x + b.x;
    o.y = (v.y - mu) * rstd * g.y + b.y;
    o.z = (v.z - mu) * rstd * g.z + b.z;
    o.w = (v.w - mu) * rstd * g.w + b.w;
    reinterpret_cast<float4*>(y + (size_t)row * D_)[tid] = o;
    if (yh) {
        unsigned h01, l01, h23, l23;
        splitpk(o.x, o.y, h01, l01);
        splitpk(o.z, o.w, h23, l23);
        const size_t i = (size_t)row * 128 + tid;
        yh[i] = ((ull)h23 << 32) | h01;
        yl[i] = ((ull)l23 << 32) | l01;
    }
}

// ---------------------------------------------------------------------------
// HMMA NT GEMM (bf16 split), cp.async loads, 2 CTAs/SM.
// ---------------------------------------------------------------------------
#define GOAH 0
#define GOAL TS
#define GOWH (2*TS)
#define GOWL (3*TS)
#define GEMM_SMEM (4*TS)   // 73728 B

__global__ __launch_bounds__(256, 2) void gemm_tc(
    const ull* __restrict__ Ah, const ull* __restrict__ Al,
    const ull* __restrict__ Wh, const ull* __restrict__ Wl,
    __nv_bfloat16* __restrict__ Ch, __nv_bfloat16* __restrict__ Cl)
{
    extern __shared__ char smc[];
    const unsigned sbase = smem_u32(smc);
    const int tid = threadIdx.x;
    const int lane = tid & 31;
    const int w = tid >> 5;
    const int m0 = blockIdx.y * 128;
    const int n0 = blockIdx.x * 128;

    float Ca[16][4];
    #pragma unroll
    for (int nb = 0; nb < 16; nb++)
        #pragma unroll
        for (int r = 0; r < 4; r++) Ca[nb][r] = 0.f;

    const unsigned a_off = (unsigned)((lane & 15) * TSB + (lane >> 4) * 16) + (unsigned)(w * 16 * TSB);
    const unsigned b_off = (unsigned)((((lane >> 4) * 8) + (lane & 7)) * TSB + ((lane >> 3) & 1) * 16);

    for (int c = 0; c < 8; c++) {
        const size_t abase = (size_t)m0 * 128 + c * 16;
        const size_t wbase = (size_t)n0 * 128 + c * 16;
        cpa_tile(sbase + GOAH, Ah, abase, tid);
        cpa_tile(sbase + GOAL, Al, abase, tid);
        cpa_tile(sbase + GOWH, Wh, wbase, tid);
        cpa_tile(sbase + GOWL, Wl, wbase, tid);
        CPA_COMMIT();
        CPA_WAIT(0);
        __syncthreads();

        unsigned aha[4][4], ala[4][4];
        #pragma unroll
        for (int ks = 0; ks < 4; ks++) {
            LDSM4(aha[ks][0], aha[ks][1], aha[ks][2], aha[ks][3], sbase + GOAH + a_off + ks*32);
            LDSM4(ala[ks][0], ala[ks][1], ala[ks][2], ala[ks][3], sbase + GOAL + a_off + ks*32);
        }
        #pragma unroll
        for (int jbp = 0; jbp < 8; jbp++) {
            #pragma unroll
            for (int ks = 0; ks < 4; ks++) {
                unsigned bh0,bh1,bh2,bh3, bl0,bl1,bl2,bl3;
                LDSM4(bh0,bh1,bh2,bh3, sbase + GOWH + (unsigned)(jbp*16*TSB) + ks*32 + b_off);
                LDSM4(bl0,bl1,bl2,bl3, sbase + GOWL + (unsigned)(jbp*16*TSB) + ks*32 + b_off);
                MMA_BF16(Ca[2*jbp],   aha[ks], bh0, bh1);
                MMA_BF16(Ca[2*jbp],   aha[ks], bl0, bl1);
                MMA_BF16(Ca[2*jbp],   ala[ks], bh0, bh1);
                MMA_BF16(Ca[2*jbp+1], aha[ks], bh2, bh3);
                MMA_BF16(Ca[2*jbp+1], aha[ks], bl2, bl3);
                MMA_BF16(Ca[2*jbp+1], ala[ks], bh2, bh3);
            }
        }
        __syncthreads();
    }

    const int g = lane >> 2, t = lane & 3;
    const int r0 = m0 + w * 16 + g;
    const int r1 = r0 + 8;
    #pragma unroll
    for (int nb = 0; nb < 16; nb++) {
        const int col = n0 + nb * 8 + 2 * t;
        unsigned h01, l01, h23, l23;
        splitpk(Ca[nb][0], Ca[nb][1], h01, l01);
        splitpk(Ca[nb][2], Ca[nb][3], h23, l23);
        *(unsigned*)&Ch[(size_t)r0 * D_ + col] = h01;
        *(unsigned*)&Cl[(size_t)r0 * D_ + col] = l01;
        *(unsigned*)&Ch[(size_t)r1 * D_ + col] = h23;
        *(unsigned*)&Cl[(size_t)r1 * D_ + col] = l23;
    }
}

// ---------------------------------------------------------------------------
// HMMA attention with double-buffered cp.async Q/V pipeline.
// smem tiles: [0]=Kh [1]=Kl | buf0: [2]=Qh [3]=Ql [4]=Vh [5]=Vl | buf1: [6..9]
// ---------------------------------------------------------------------------
#define ATTN_SMEM (10*TS)   // 184320 B

__global__ __launch_bounds__(256, 1) void attn_tc(
    const ull* __restrict__ Qh, const ull* __restrict__ Ql,
    const ull* __restrict__ Kh, const ull* __restrict__ Kl,
    const ull* __restrict__ Vh, const ull* __restrict__ Vl,
    float* __restrict__ O)
{
    extern __shared__ char smc[];
    const unsigned sbase = smem_u32(smc);
    const int tid = threadIdx.x;
    const int lane = tid & 31;
    const int w = tid >> 5;
    const int it = blockIdx.x;
    const int bh = blockIdx.y;
    const int b = bh >> 3, h = bh & 7;
    const size_t base = (size_t)b * S_ * D_ + (size_t)h * HD;
    const size_t base4 = base >> 2;
    const int i0 = it * 128;

    // prologue: async-load K tile, then Q/V tile 0 into buf0
    cpa_tile(sbase + 0*TS, Kh, base4 + (size_t)i0 * 128, tid);
    cpa_tile(sbase + 1*TS, Kl, base4 + (size_t)i0 * 128, tid);
    CPA_COMMIT();
    {
        const size_t rb = base4;
        cpa_tile(sbase + 2*TS, Qh, rb, tid);
        cpa_tile(sbase + 3*TS, Ql, rb, tid);
        cpa_tile(sbase + 4*TS, Vh, rb, tid);
        cpa_tile(sbase + 5*TS, Vl, rb, tid);
    }
    CPA_COMMIT();
    CPA_WAIT(1);           // K ready (QV0 may still be in flight)
    __syncthreads();

    // persistent K fragments
    const unsigned a_off = (unsigned)((lane & 15) * TSB + (lane >> 4) * 16) + (unsigned)(w * 16 * TSB);
    unsigned kha[4][4], kla[4][4];
    #pragma unroll
    for (int ks = 0; ks < 4; ks++) {
        LDSM4(kha[ks][0], kha[ks][1], kha[ks][2], kha[ks][3], sbase + 0*TS + a_off + ks*32);
        LDSM4(kla[ks][0], kla[ks][1], kla[ks][2], kla[ks][3], sbase + 1*TS + a_off + ks*32);
    }

    const unsigned b_off = (unsigned)((((lane >> 4) * 8) + (lane & 7)) * TSB + ((lane >> 3) & 1) * 16);
    const unsigned v_off = (unsigned)(((((lane >> 3) & 1) * 8) + (lane & 7)) * TSB + (lane >> 4) * 16);

    float Oa[8][4];
    #pragma unroll
    for (int db = 0; db < 8; db++)
        #pragma unroll
        for (int r = 0; r < 4; r++) Oa[db][r] = 0.f;
    float m0 = -1e30f, m1 = -1e30f, lsum0 = 0.f, lsum1 = 0.f;

    for (int jt = 0; jt < 16; jt++) {
        // prefetch next Q/V tile into the other buffer
        if (jt < 15) {
            const int nb_ = (jt + 1) & 1;
            const size_t rb = base4 + (size_t)(jt + 1) * 128 * 128;
            cpa_tile(sbase + (unsigned)((2 + 4*nb_) * TS), Qh, rb, tid);
            cpa_tile(sbase + (unsigned)((3 + 4*nb_) * TS), Ql, rb, tid);
            cpa_tile(sbase + (unsigned)((4 + 4*nb_) * TS), Vh, rb, tid);
            cpa_tile(sbase + (unsigned)((5 + 4*nb_) * TS), Vl, rb, tid);
            CPA_COMMIT();
            CPA_WAIT(1);   // current tile (group jt) complete
        } else {
            CPA_WAIT(0);
        }
        __syncthreads();

        const int bb = jt & 1;
        const unsigned qh_b = sbase + (unsigned)((2 + 4*bb) * TS);
        const unsigned ql_b = sbase + (unsigned)((3 + 4*bb) * TS);
        const unsigned vh_b = sbase + (unsigned)((4 + 4*bb) * TS);
        const unsigned vl_b = sbase + (unsigned)((5 + 4*bb) * TS);

        // ---- S = K @ Q^T ----
        float Sa[16][4];
        #pragma unroll
        for (int nb = 0; nb < 16; nb++)
            #pragma unroll
            for (int r = 0; r < 4; r++) Sa[nb][r] = 0.f;

        #pragma unroll
        for (int jbp = 0; jbp < 8; jbp++) {
            #pragma unroll
            for (int ks = 0; ks < 4; ks++) {
                unsigned bh0,bh1,bh2,bh3, bl0,bl1,bl2,bl3;
                LDSM4(bh0,bh1,bh2,bh3, qh_b + (unsigned)(jbp*16*TSB) + ks*32 + b_off);
                LDSM4(bl0,bl1,bl2,bl3, ql_b + (unsigned)(jbp*16*TSB) + ks*32 + b_off);
                MMA_BF16(Sa[2*jbp],   kha[ks], bh0, bh1);
                MMA_BF16(Sa[2*jbp],   kha[ks], bl0, bl1);
                MMA_BF16(Sa[2*jbp],   kla[ks], bh0, bh1);
                MMA_BF16(Sa[2*jbp+1], kha[ks], bh2, bh3);
                MMA_BF16(Sa[2*jbp+1], kha[ks], bl2, bl3);
                MMA_BF16(Sa[2*jbp+1], kla[ks], bh2, bh3);
            }
        }

        // ---- online softmax ----
        float mx0 = -1e30f, mx1 = -1e30f;
        #pragma unroll
        for (int nb = 0; nb < 16; nb++) {
            mx0 = fmaxf(mx0, fmaxf(Sa[nb][0], Sa[nb][1]));
            mx1 = fmaxf(mx1, fmaxf(Sa[nb][2], Sa[nb][3]));
        }
        mx0 = fmaxf(mx0, __shfl_xor_sync(0xffffffffu, mx0, 1));
        mx0 = fmaxf(mx0, __shfl_xor_sync(0xffffffffu, mx0, 2));
        mx1 = fmaxf(mx1, __shfl_xor_sync(0xffffffffu, mx1, 1));
        mx1 = fmaxf(mx1, __shfl_xor_sync(0xffffffffu, mx1, 2));
        const float mn0 = fmaxf(m0, mx0);
        const float mn1 = fmaxf(m1, mx1);
        const float al0 = __expf(m0 - mn0);
        const float al1 = __expf(m1 - mn1);
        float rs0 = 0.f, rs1 = 0.f;
        #pragma unroll
        for (int nb = 0; nb < 16; nb++) {
            Sa[nb][0] = __expf(Sa[nb][0] - mn0);
            Sa[nb][1] = __expf(Sa[nb][1] - mn0);
            Sa[nb][2] = __expf(Sa[nb][2] - mn1);
            Sa[nb][3] = __expf(Sa[nb][3] - mn1);
            rs0 += Sa[nb][0] + Sa[nb][1];
            rs1 += Sa[nb][2] + Sa[nb][3];
        }
        rs0 += __shfl_xor_sync(0xffffffffu, rs0, 1);
        rs0 += __shfl_xor_sync(0xffffffffu, rs0, 2);
        rs1 += __shfl_xor_sync(0xffffffffu, rs1, 1);
        rs1 += __shfl_xor_sync(0xffffffffu, rs1, 2);
        lsum0 = lsum0 * al0 + rs0;  m0 = mn0;
        lsum1 = lsum1 * al1 + rs1;  m1 = mn1;
        #pragma unroll
        for (int db = 0; db < 8; db++) {
            Oa[db][0] *= al0; Oa[db][1] *= al0;
            Oa[db][2] *= al1; Oa[db][3] *= al1;
        }

        // ---- O += P @ V ----
        #pragma unroll
        for (int ks = 0; ks < 8; ks++) {
            unsigned pah[4], pal[4];
            splitpk(Sa[2*ks][0],   Sa[2*ks][1],   pah[0], pal[0]);
            splitpk(Sa[2*ks][2],   Sa[2*ks][3],   pah[1], pal[1]);
            splitpk(Sa[2*ks+1][0], Sa[2*ks+1][1], pah[2], pal[2]);
            splitpk(Sa[2*ks+1][2], Sa[2*ks+1][3], pah[3], pal[3]);
            #pragma unroll
            for (int dbp = 0; dbp < 4; dbp++) {
                unsigned vh0,vh1,vh2,vh3, vl0,vl1,vl2,vl3;
                LDSM4T(vh0,vh1,vh2,vh3, vh_b + (unsigned)(ks*16*TSB) + dbp*32 + v_off);
                LDSM4T(vl0,vl1,vl2,vl3, vl_b + (unsigned)(ks*16*TSB) + dbp*32 + v_off);
                MMA_BF16(Oa[2*dbp],   pah, vh0, vh1);
                MMA_BF16(Oa[2*dbp],   pah, vl0, vl1);
                MMA_BF16(Oa[2*dbp],   pal, vh0, vh1);
                MMA_BF16(Oa[2*dbp+1], pah, vh2, vh3);
                MMA_BF16(Oa[2*dbp+1], pah, vl2, vl3);
                MMA_BF16(Oa[2*dbp+1], pal, vh2, vh3);
            }
        }
        __syncthreads();
    }

    // ---- normalize + write ----
    const float inv0 = 1.0f / lsum0;
    const float inv1 = 1.0f / lsum1;
    const int g = lane >> 2, t = lane & 3;
    const int r0 = i0 + w * 16 + g;
    const int r1 = r0 + 8;
    #pragma unroll
    for (int db = 0; db < 8; db++) {
        const int col = db * 8 + 2 * t;
        *(float2*)&O[base + (size_t)r0 * D_ + col] = make_float2(Oa[db][0]*inv0, Oa[db][1]*inv0);
        *(float2*)&O[base + (size_t)r1 * D_ + col] = make_float2(Oa[db][2]*inv1, Oa[db][3]*inv1);
    }
}

// ---------------------------------------------------------------------------
extern "C" void kernel_launch(void* const* d_in, const int* in_sizes, int n_in,
                              void* d_out, int out_size)
{
    const float* seq_k = (const float*)d_in[0];
    const float* seq_q = (const float*)d_in[1];
    const float* seq_v = (const float*)d_in[2];
    const float* W1    = (const float*)d_in[3];
    const float* W2    = (const float*)d_in[4];
    const float* W3    = (const float*)d_in[5];
    const float* gamma = (const float*)d_in[6];
    const float* beta  = (const float*)d_in[7];
    float* out = (float*)d_out;

    float *vin, *att;
    ull *sqh,*sql,*skh,*skl,*svh,*svl,*w1h,*w1l,*w2h,*w2l,*w3h,*w3l;
    ull *qh,*ql,*kh,*kl,*vh,*vl;
    cudaGetSymbolAddress((void**)&vin, g_vin);
    cudaGetSymbolAddress((void**)&att, g_att);
    cudaGetSymbolAddress((void**)&sqh, g_sqh); cudaGetSymbolAddress((void**)&sql, g_sql);
    cudaGetSymbolAddress((void**)&skh, g_skh); cudaGetSymbolAddress((void**)&skl, g_skl);
    cudaGetSymbolAddress((void**)&svh, g_svh); cudaGetSymbolAddress((void**)&svl, g_svl);
    cudaGetSymbolAddress((void**)&w1h, g_w1h); cudaGetSymbolAddress((void**)&w1l, g_w1l);
    cudaGetSymbolAddress((void**)&w2h, g_w2h); cudaGetSymbolAddress((void**)&w2l, g_w2l);
    cudaGetSymbolAddress((void**)&w3h, g_w3h); cudaGetSymbolAddress((void**)&w3l, g_w3l);
    cudaGetSymbolAddress((void**)&qh,  g_qh);  cudaGetSymbolAddress((void**)&ql,  g_ql);
    cudaGetSymbolAddress((void**)&kh,  g_kh);  cudaGetSymbolAddress((void**)&kl,  g_kl);
    cudaGetSymbolAddress((void**)&vh,  g_vh);  cudaGetSymbolAddress((void**)&vl,  g_vl);

    // 1) v_in = LN(seq_v), fused split to bf16 hi/lo
    ln_kernel<<<M_, 128>>>(seq_v, nullptr, gamma, beta, vin, svh, svl);

    // 2) split q/k inputs + weights
    const int n4i = M_ * D_ / 4;
    const int n4w = D_ * D_ / 4;
    split_kernel<<<n4i/256, 256>>>((const float4*)seq_q, sqh, sql, n4i);
    split_kernel<<<n4i/256, 256>>>((const float4*)seq_k, skh, skl, n4i);
    split_kernel<<<n4w/256, 256>>>((const float4*)W1,    w1h, w1l, n4w);
    split_kernel<<<n4w/256, 256>>>((const float4*)W2,    w2h, w2l, n4w);
    split_kernel<<<n4w/256, 256>>>((const float4*)W3,    w3h, w3l, n4w);

    // 3) projections on HMMA
    cudaFuncSetAttribute(gemm_tc, cudaFuncAttributeMaxDynamicSharedMemorySize, GEMM_SMEM);
    dim3 ggrid(D_ / 128, M_ / 128);
    gemm_tc<<<ggrid, 256, GEMM_SMEM>>>(sqh, sql, w1h, w1l, (__nv_bfloat16*)qh, (__nv_bfloat16*)ql);
    gemm_tc<<<ggrid, 256, GEMM_SMEM>>>(skh, skl, w2h, w2l, (__nv_bfloat16*)kh, (__nv_bfloat16*)kl);
    gemm_tc<<<ggrid, 256, GEMM_SMEM>>>(svh, svl, w3h, w3l, (__nv_bfloat16*)vh, (__nv_bfloat16*)vl);

    // 4) attention on HMMA (pipelined)
    cudaFuncSetAttribute(attn_tc, cudaFuncAttributeMaxDynamicSharedMemorySize, ATTN_SMEM);
    attn_tc<<<dim3(S_ / 128, B_ * H_), 256, ATTN_SMEM>>>(qh, ql, kh, kl, vh, vl, att);

    // 5) out = LN(att + v_in)
    ln_kernel<<<M_, 128>>>(att, vin, gamma, beta, out, nullptr, nullptr);
}

// round 6
// speedup vs baseline: 3.8934x; 1.0168x over previous
#include <cuda_runtime.h>
#include <cuda_bf16.h>
#include <math.h>

#define B_ 4
#define S_ 2048
#define D_ 512
#define H_ 8
#define HD 64
#define M_ (B_*S_)
#define EPS_ 1e-5f

typedef unsigned long long ull;

// ---------------------------------------------------------------------------
// Scratch (__device__ globals; allocation-free rule)
// ---------------------------------------------------------------------------
__device__ float g_vin[(size_t)M_*D_];
__device__ float g_att[(size_t)M_*D_];
__device__ ull g_sqh[M_*D_/4], g_sql[M_*D_/4];
__device__ ull g_skh[M_*D_/4], g_skl[M_*D_/4];
__device__ ull g_svh[M_*D_/4], g_svl[M_*D_/4];
__device__ ull g_w1h[D_*D_/4], g_w1l[D_*D_/4];
__device__ ull g_w2h[D_*D_/4], g_w2l[D_*D_/4];
__device__ ull g_w3h[D_*D_/4], g_w3l[D_*D_/4];
__device__ ull g_qh[M_*D_/4], g_ql[M_*D_/4];
__device__ ull g_kh[M_*D_/4], g_kl[M_*D_/4];
__device__ ull g_vh[M_*D_/4], g_vl[M_*D_/4];

// ---------------------------------------------------------------------------
// helpers
// ---------------------------------------------------------------------------
__device__ __forceinline__ unsigned smem_u32(const void* p) {
    unsigned r;
    asm("{ .reg .u64 t; cvta.to.shared.u64 t, %1; cvt.u32.u64 %0, t; }"
        : "=r"(r) : "l"(p));
    return r;
}
__device__ __forceinline__ void splitpk(float x, float y, unsigned& hp, unsigned& lp) {
    __nv_bfloat16 hx = __float2bfloat16(x), hy = __float2bfloat16(y);
    float rx = x - __bfloat162float(hx), ry = y - __bfloat162float(hy);
    __nv_bfloat16 lx = __float2bfloat16(rx), ly = __float2bfloat16(ry);
    hp = ((unsigned)__bfloat16_as_ushort(hy) << 16) | (unsigned)__bfloat16_as_ushort(hx);
    lp = ((unsigned)__bfloat16_as_ushort(ly) << 16) | (unsigned)__bfloat16_as_ushort(lx);
}

#define MMA_BF16(c, a, b0, b1) \
    asm volatile("mma.sync.aligned.m16n8k16.row.col.f32.bf16.bf16.f32 " \
        "{%0,%1,%2,%3}, {%4,%5,%6,%7}, {%8,%9}, {%0,%1,%2,%3};" \
        : "+f"((c)[0]), "+f"((c)[1]), "+f"((c)[2]), "+f"((c)[3]) \
        : "r"((a)[0]), "r"((a)[1]), "r"((a)[2]), "r"((a)[3]), "r"(b0), "r"(b1))

#define LDSM4(r0,r1,r2,r3,addr) \
    asm volatile("ldmatrix.sync.aligned.m8n8.x4.shared.b16 {%0,%1,%2,%3}, [%4];" \
        : "=r"(r0),"=r"(r1),"=r"(r2),"=r"(r3) : "r"(addr))
#define LDSM4T(r0,r1,r2,r3,addr) \
    asm volatile("ldmatrix.sync.aligned.m8n8.x4.trans.shared.b16 {%0,%1,%2,%3}, [%4];" \
        : "=r"(r0),"=r"(r1),"=r"(r2),"=r"(r3) : "r"(addr))

__device__ __forceinline__ void cpa16(unsigned sa, const void* ga) {
    asm volatile("cp.async.cg.shared.global [%0], [%1], 16;" :: "r"(sa), "l"(ga) : "memory");
}
#define CPA_COMMIT() asm volatile("cp.async.commit_group;" ::: "memory")
#define CPA_WAIT(n)  asm volatile("cp.async.wait_group %0;" :: "n"(n) : "memory")

// bf16 tile row stride: 64 elems (128B) + 16B pad = 144B (LDSM conflict-free)
#define TSB 144
#define TSK (128*TSB)   // 128x64 tile  (18432 B)
#define TSQ (64*TSB)    //  64x64 tile  ( 9216 B)

// async-copy an R x 64 bf16 tile (16 ull/row in gmem) into padded smem
template<int R>
__device__ __forceinline__ void cpa_tile(unsigned dst, const ull* __restrict__ src,
                                         size_t rowbase, int tid) {
    #pragma unroll
    for (int l = 0; l < R/32; l++) {
        const int idx = tid + l * 256;
        const int r = idx >> 3, c8 = idx & 7;
        cpa16(dst + (unsigned)(r * TSB + c8 * 16), src + rowbase + (size_t)r * 128 + c8 * 2);
    }
}

// ---------------------------------------------------------------------------
// merged split kernels
// ---------------------------------------------------------------------------
__global__ __launch_bounds__(256) void split_in_kernel(
    const float4* __restrict__ xq, ull* __restrict__ qh, ull* __restrict__ ql,
    const float4* __restrict__ xk, ull* __restrict__ kh, ull* __restrict__ kl, int n4)
{
    int i = blockIdx.x * 256 + threadIdx.x;
    const float4* x; ull *hi, *lo;
    if (i < n4) { x = xq; hi = qh; lo = ql; }
    else        { x = xk; hi = kh; lo = kl; i -= n4; }
    float4 v = x[i];
    unsigned h01, l01, h23, l23;
    splitpk(v.x, v.y, h01, l01);
    splitpk(v.z, v.w, h23, l23);
    hi[i] = ((ull)h23 << 32) | h01;
    lo[i] = ((ull)l23 << 32) | l01;
}

__global__ __launch_bounds__(256) void split_w_kernel(
    const float4* __restrict__ w1, ull* __restrict__ w1h, ull* __restrict__ w1l,
    const float4* __restrict__ w2, ull* __restrict__ w2h, ull* __restrict__ w2l,
    const float4* __restrict__ w3, ull* __restrict__ w3h, ull* __restrict__ w3l, int n4)
{
    int i = blockIdx.x * 256 + threadIdx.x;
    const float4* x; ull *hi, *lo;
    if (i < n4)          { x = w1; hi = w1h; lo = w1l; }
    else if (i < 2*n4)   { x = w2; hi = w2h; lo = w2l; i -= n4; }
    else                 { x = w3; hi = w3h; lo = w3l; i -= 2*n4; }
    float4 v = x[i];
    unsigned h01, l01, h23, l23;
    splitpk(v.x, v.y, h01, l01);
    splitpk(v.z, v.w, h23, l23);
    hi[i] = ((ull)h23 << 32) | h01;
    lo[i] = ((ull)l23 << 32) | l01;
}

// ---------------------------------------------------------------------------
// LayerNorm; optionally also emits split bf16 hi/lo of the result.
// ---------------------------------------------------------------------------
__global__ __launch_bounds__(128) void ln_kernel(
    const float* __restrict__ x, const float* __restrict__ res,
    const float* __restrict__ gamma, const float* __restrict__ beta,
    float* __restrict__ y, ull* __restrict__ yh, ull* __restrict__ yl)
{
    const int row = blockIdx.x;
    const int tid = threadIdx.x;
    const float4* x4 = reinterpret_cast<const float4*>(x + (size_t)row * D_);
    float4 v = x4[tid];
    if (res) {
        const float4* r4 = reinterpret_cast<const float4*>(res + (size_t)row * D_);
        float4 r = r4[tid];
        v.x += r.x; v.y += r.y; v.z += r.z; v.w += r.w;
    }
    float s  = v.x + v.y + v.z + v.w;
    float ss = v.x*v.x + v.y*v.y + v.z*v.z + v.w*v.w;
    #pragma unroll
    for (int o = 16; o > 0; o >>= 1) {
        s  += __shfl_xor_sync(0xffffffffu, s,  o);
        ss += __shfl_xor_sync(0xffffffffu, ss, o);
    }
    __shared__ float sb[4], ssb[4];
    const int w = tid >> 5;
    if ((tid & 31) == 0) { sb[w] = s; ssb[w] = ss; }
    __syncthreads();
    s  = sb[0]  + sb[1]  + sb[2]  + sb[3];
    ss = ssb[0] + ssb[1] + ssb[2] + ssb[3];
    const float mu   = s * (1.0f / D_);
    const float var  = ss * (1.0f / D_) - mu * mu;
    const float rstd = rsqrtf(var + EPS_);
    const float4 g = reinterpret_cast<const float4*>(gamma)[tid];
    const float4 b = reinterpret_cast<const float4*>(beta )[tid];
    float4 o;
    o.x = (v.x - mu) * rstd * g.x + b.x;
    o.y = (v.y - mu) * rstd * g.y + b.y;
    o.z = (v.z - mu) * rstd * g.z + b.z;
    o.w = (v.w - mu) * rstd * g.w + b.w;
    reinterpret_cast<float4*>(y + (size_t)row * D_)[tid] = o;
    if (yh) {
        unsigned h01, l01, h23, l23;
        splitpk(o.x, o.y, h01, l01);
        splitpk(o.z, o.w, h23, l23);
        const size_t i = (size_t)row * 128 + tid;
        yh[i] = ((ull)h23 << 32) | h01;
        yl[i] = ((ull)l23 << 32) | l01;
    }
}

// ---------------------------------------------------------------------------
// HMMA NT GEMM, 3-in-1 (blockIdx.z selects projection), cp.async, 2 CTAs/SM.
// ---------------------------------------------------------------------------
#define GOAH 0
#define GOAL TSK
#define GOWH (2*TSK)
#define GOWL (3*TSK)
#define GEMM_SMEM (4*TSK)   // 73728 B

__global__ __launch_bounds__(256, 2) void gemm_tc(
    const ull* __restrict__ A0h, const ull* __restrict__ A0l,
    const ull* __restrict__ W0h, const ull* __restrict__ W0l,
    __nv_bfloat16* __restrict__ C0h, __nv_bfloat16* __restrict__ C0l,
    const ull* __restrict__ A1h, const ull* __restrict__ A1l,
    const ull* __restrict__ W1h_, const ull* __restrict__ W1l_,
    __nv_bfloat16* __restrict__ C1h, __nv_bfloat16* __restrict__ C1l,
    const ull* __restrict__ A2h, const ull* __restrict__ A2l,
    const ull* __restrict__ W2h_, const ull* __restrict__ W2l_,
    __nv_bfloat16* __restrict__ C2h, __nv_bfloat16* __restrict__ C2l)
{
    const ull *Ah, *Al, *Wh, *Wl;
    __nv_bfloat16 *Ch, *Cl;
    if (blockIdx.z == 0)      { Ah=A0h; Al=A0l; Wh=W0h;  Wl=W0l;  Ch=C0h; Cl=C0l; }
    else if (blockIdx.z == 1) { Ah=A1h; Al=A1l; Wh=W1h_; Wl=W1l_; Ch=C1h; Cl=C1l; }
    else                      { Ah=A2h; Al=A2l; Wh=W2h_; Wl=W2l_; Ch=C2h; Cl=C2l; }

    extern __shared__ char smc[];
    const unsigned sbase = smem_u32(smc);
    const int tid = threadIdx.x;
    const int lane = tid & 31;
    const int w = tid >> 5;
    const int m0 = blockIdx.y * 128;
    const int n0 = blockIdx.x * 128;

    float Ca[16][4];
    #pragma unroll
    for (int nb = 0; nb < 16; nb++)
        #pragma unroll
        for (int r = 0; r < 4; r++) Ca[nb][r] = 0.f;

    const unsigned a_off = (unsigned)((lane & 15) * TSB + (lane >> 4) * 16) + (unsigned)(w * 16 * TSB);
    const unsigned b_off = (unsigned)((((lane >> 4) * 8) + (lane & 7)) * TSB + ((lane >> 3) & 1) * 16);

    for (int c = 0; c < 8; c++) {
        const size_t abase = (size_t)m0 * 128 + c * 16;
        const size_t wbase = (size_t)n0 * 128 + c * 16;
        cpa_tile<128>(sbase + GOAH, Ah, abase, tid);
        cpa_tile<128>(sbase + GOAL, Al, abase, tid);
        cpa_tile<128>(sbase + GOWH, Wh, wbase, tid);
        cpa_tile<128>(sbase + GOWL, Wl, wbase, tid);
        CPA_COMMIT();
        CPA_WAIT(0);
        __syncthreads();

        unsigned aha[4][4], ala[4][4];
        #pragma unroll
        for (int ks = 0; ks < 4; ks++) {
            LDSM4(aha[ks][0], aha[ks][1], aha[ks][2], aha[ks][3], sbase + GOAH + a_off + ks*32);
            LDSM4(ala[ks][0], ala[ks][1], ala[ks][2], ala[ks][3], sbase + GOAL + a_off + ks*32);
        }
        #pragma unroll
        for (int jbp = 0; jbp < 8; jbp++) {
            #pragma unroll
            for (int ks = 0; ks < 4; ks++) {
                unsigned bh0,bh1,bh2,bh3, bl0,bl1,bl2,bl3;
                LDSM4(bh0,bh1,bh2,bh3, sbase + GOWH + (unsigned)(jbp*16*TSB) + ks*32 + b_off);
                LDSM4(bl0,bl1,bl2,bl3, sbase + GOWL + (unsigned)(jbp*16*TSB) + ks*32 + b_off);
                MMA_BF16(Ca[2*jbp],   aha[ks], bh0, bh1);
                MMA_BF16(Ca[2*jbp],   aha[ks], bl0, bl1);
                MMA_BF16(Ca[2*jbp],   ala[ks], bh0, bh1);
                MMA_BF16(Ca[2*jbp+1], aha[ks], bh2, bh3);
                MMA_BF16(Ca[2*jbp+1], aha[ks], bl2, bl3);
                MMA_BF16(Ca[2*jbp+1], ala[ks], bh2, bh3);
            }
        }
        __syncthreads();
    }

    const int g = lane >> 2, t = lane & 3;
    const int r0 = m0 + w * 16 + g;
    const int r1 = r0 + 8;
    #pragma unroll
    for (int nb = 0; nb < 16; nb++) {
        const int col = n0 + nb * 8 + 2 * t;
        unsigned h01, l01, h23, l23;
        splitpk(Ca[nb][0], Ca[nb][1], h01, l01);
        splitpk(Ca[nb][2], Ca[nb][3], h23, l23);
        *(unsigned*)&Ch[(size_t)r0 * D_ + col] = h01;
        *(unsigned*)&Cl[(size_t)r0 * D_ + col] = l01;
        *(unsigned*)&Ch[(size_t)r1 * D_ + col] = h23;
        *(unsigned*)&Cl[(size_t)r1 * D_ + col] = l23;
    }
}

// ---------------------------------------------------------------------------
// HMMA attention, BJ=64 tiles, double-buffered cp.async, 2 CTAs/SM.
// smem: Kh,Kl (128x64 each) | buf{0,1}: Qh,Ql,Vh,Vl (64x64 each)
// ---------------------------------------------------------------------------
#define AQV(buf, t) (2*TSK + (buf)*4*TSQ + (t)*TSQ)
#define ATTN_SMEM (2*TSK + 8*TSQ)   // 110592 B

__global__ __launch_bounds__(256, 2) void attn_tc(
    const ull* __restrict__ Qh, const ull* __restrict__ Ql,
    const ull* __restrict__ Kh, const ull* __restrict__ Kl,
    const ull* __restrict__ Vh, const ull* __restrict__ Vl,
    float* __restrict__ O)
{
    extern __shared__ char smc[];
    const unsigned sbase = smem_u32(smc);
    const int tid = threadIdx.x;
    const int lane = tid & 31;
    const int w = tid >> 5;
    const int it = blockIdx.x;
    const int bh = blockIdx.y;
    const int b = bh >> 3, h = bh & 7;
    const size_t base = (size_t)b * S_ * D_ + (size_t)h * HD;
    const size_t base4 = base >> 2;
    const int i0 = it * 128;

    // prologue: K tile, then Q/V j-tile 0 into buf0
    cpa_tile<128>(sbase + 0*TSK, Kh, base4 + (size_t)i0 * 128, tid);
    cpa_tile<128>(sbase + 1*TSK, Kl, base4 + (size_t)i0 * 128, tid);
    CPA_COMMIT();
    cpa_tile<64>(sbase + AQV(0,0), Qh, base4, tid);
    cpa_tile<64>(sbase + AQV(0,1), Ql, base4, tid);
    cpa_tile<64>(sbase + AQV(0,2), Vh, base4, tid);
    cpa_tile<64>(sbase + AQV(0,3), Vl, base4, tid);
    CPA_COMMIT();
    CPA_WAIT(1);
    __syncthreads();

    // persistent K fragments
    const unsigned a_off = (unsigned)((lane & 15) * TSB + (lane >> 4) * 16) + (unsigned)(w * 16 * TSB);
    unsigned kha[4][4], kla[4][4];
    #pragma unroll
    for (int ks = 0; ks < 4; ks++) {
        LDSM4(kha[ks][0], kha[ks][1], kha[ks][2], kha[ks][3], sbase + 0*TSK + a_off + ks*32);
        LDSM4(kla[ks][0], kla[ks][1], kla[ks][2], kla[ks][3], sbase + 1*TSK + a_off + ks*32);
    }

    const unsigned b_off = (unsigned)((((lane >> 4) * 8) + (lane & 7)) * TSB + ((lane >> 3) & 1) * 16);
    const unsigned v_off = (unsigned)(((((lane >> 3) & 1) * 8) + (lane & 7)) * TSB + (lane >> 4) * 16);

    float Oa[8][4];
    #pragma unroll
    for (int db = 0; db < 8; db++)
        #pragma unroll
        for (int r = 0; r < 4; r++) Oa[db][r] = 0.f;
    float m0 = -1e30f, m1 = -1e30f, lsum0 = 0.f, lsum1 = 0.f;

    for (int jt = 0; jt < 32; jt++) {
        if (jt < 31) {
            const int nb_ = (jt + 1) & 1;
            const size_t rb = base4 + (size_t)(jt + 1) * 64 * 128;
            cpa_tile<64>(sbase + AQV(nb_,0), Qh, rb, tid);
            cpa_tile<64>(sbase + AQV(nb_,1), Ql, rb, tid);
            cpa_tile<64>(sbase + AQV(nb_,2), Vh, rb, tid);
            cpa_tile<64>(sbase + AQV(nb_,3), Vl, rb, tid);
            CPA_COMMIT();
            CPA_WAIT(1);
        } else {
            CPA_WAIT(0);
        }
        __syncthreads();

        const int bb = jt & 1;
        const unsigned qh_b = sbase + AQV(bb,0);
        const unsigned ql_b = sbase + AQV(bb,1);
        const unsigned vh_b = sbase + AQV(bb,2);
        const unsigned vl_b = sbase + AQV(bb,3);

        // ---- S = K @ Q^T : warp m16 x n64 ----
        float Sa[8][4];
        #pragma unroll
        for (int nb = 0; nb < 8; nb++)
            #pragma unroll
            for (int r = 0; r < 4; r++) Sa[nb][r] = 0.f;

        #pragma unroll
        for (int jbp = 0; jbp < 4; jbp++) {
            #pragma unroll
            for (int ks = 0; ks < 4; ks++) {
                unsigned bh0,bh1,bh2,bh3, bl0,bl1,bl2,bl3;
                LDSM4(bh0,bh1,bh2,bh3, qh_b + (unsigned)(jbp*16*TSB) + ks*32 + b_off);
                LDSM4(bl0,bl1,bl2,bl3, ql_b + (unsigned)(jbp*16*TSB) + ks*32 + b_off);
                MMA_BF16(Sa[2*jbp],   kha[ks], bh0, bh1);
                MMA_BF16(Sa[2*jbp],   kha[ks], bl0, bl1);
                MMA_BF16(Sa[2*jbp],   kla[ks], bh0, bh1);
                MMA_BF16(Sa[2*jbp+1], kha[ks], bh2, bh3);
                MMA_BF16(Sa[2*jbp+1], kha[ks], bl2, bl3);
                MMA_BF16(Sa[2*jbp+1], kla[ks], bh2, bh3);
            }
        }

        // ---- online softmax ----
        float mx0 = -1e30f, mx1 = -1e30f;
        #pragma unroll
        for (int nb = 0; nb < 8; nb++) {
            mx0 = fmaxf(mx0, fmaxf(Sa[nb][0], Sa[nb][1]));
            mx1 = fmaxf(mx1, fmaxf(Sa[nb][2], Sa[nb][3]));
        }
        mx0 = fmaxf(mx0, __shfl_xor_sync(0xffffffffu, mx0, 1));
        mx0 = fmaxf(mx0, __shfl_xor_sync(0xffffffffu, mx0, 2));
        mx1 = fmaxf(mx1, __shfl_xor_sync(0xffffffffu, mx1, 1));
        mx1 = fmaxf(mx1, __shfl_xor_sync(0xffffffffu, mx1, 2));
        const float mn0 = fmaxf(m0, mx0);
        const float mn1 = fmaxf(m1, mx1);
        const float al0 = __expf(m0 - mn0);
        const float al1 = __expf(m1 - mn1);
        float rs0 = 0.f, rs1 = 0.f;
        #pragma unroll
        for (int nb = 0; nb < 8; nb++) {
            Sa[nb][0] = __expf(Sa[nb][0] - mn0);
            Sa[nb][1] = __expf(Sa[nb][1] - mn0);
            Sa[nb][2] = __expf(Sa[nb][2] - mn1);
            Sa[nb][3] = __expf(Sa[nb][3] - mn1);
            rs0 += Sa[nb][0] + Sa[nb][1];
            rs1 += Sa[nb][2] + Sa[nb][3];
        }
        rs0 += __shfl_xor_sync(0xffffffffu, rs0, 1);
        rs0 += __shfl_xor_sync(0xffffffffu, rs0, 2);
        rs1 += __shfl_xor_sync(0xffffffffu, rs1, 1);
        rs1 += __shfl_xor_sync(0xffffffffu, rs1, 2);
        lsum0 = lsum0 * al0 + rs0;  m0 = mn0;
        lsum1 = lsum1 * al1 + rs1;  m1 = mn1;
        #pragma unroll
        for (int db = 0; db < 8; db++) {
            Oa[db][0] *= al0; Oa[db][1] *= al0;
            Oa[db][2] *= al1; Oa[db][3] *= al1;
        }

        // ---- O += P @ V ----
        #pragma unroll
        for (int ks = 0; ks < 4; ks++) {
            unsigned pah[4], pal[4];
            splitpk(Sa[2*ks][0],   Sa[2*ks][1],   pah[0], pal[0]);
            splitpk(Sa[2*ks][2],   Sa[2*ks][3],   pah[1], pal[1]);
            splitpk(Sa[2*ks+1][0], Sa[2*ks+1][1], pah[2], pal[2]);
            splitpk(Sa[2*ks+1][2], Sa[2*ks+1][3], pah[3], pal[3]);
            #pragma unroll
            for (int dbp = 0; dbp < 4; dbp++) {
                unsigned vh0,vh1,vh2,vh3, vl0,vl1,vl2,vl3;
                LDSM4T(vh0,vh1,vh2,vh3, vh_b + (unsigned)(ks*16*TSB) + dbp*32 + v_off);
                LDSM4T(vl0,vl1,vl2,vl3, vl_b + (unsigned)(ks*16*TSB) + dbp*32 + v_off);
                MMA_BF16(Oa[2*dbp],   pah, vh0, vh1);
                MMA_BF16(Oa[2*dbp],   pah, vl0, vl1);
                MMA_BF16(Oa[2*dbp],   pal, vh0, vh1);
                MMA_BF16(Oa[2*dbp+1], pah, vh2, vh3);
                MMA_BF16(Oa[2*dbp+1], pah, vl2, vl3);
                MMA_BF16(Oa[2*dbp+1], pal, vh2, vh3);
            }
        }
        __syncthreads();
    }

    // ---- normalize + write ----
    const float inv0 = 1.0f / lsum0;
    const float inv1 = 1.0f / lsum1;
    const int g = lane >> 2, t = lane & 3;
    const int r0 = i0 + w * 16 + g;
    const int r1 = r0 + 8;
    #pragma unroll
    for (int db = 0; db < 8; db++) {
        const int col = db * 8 + 2 * t;
        *(float2*)&O[base + (size_t)r0 * D_ + col] = make_float2(Oa[db][0]*inv0, Oa[db][1]*inv0);
        *(float2*)&O[base + (size_t)r1 * D_ + col] = make_float2(Oa[db][2]*inv1, Oa[db][3]*inv1);
    }
}

// ---------------------------------------------------------------------------
extern "C" void kernel_launch(void* const* d_in, const int* in_sizes, int n_in,
                              void* d_out, int out_size)
{
    const float* seq_k = (const float*)d_in[0];
    const float* seq_q = (const float*)d_in[1];
    const float* seq_v = (const float*)d_in[2];
    const float* W1    = (const float*)d_in[3];
    const float* W2    = (const float*)d_in[4];
    const float* W3    = (const float*)d_in[5];
    const float* gamma = (const float*)d_in[6];
    const float* beta  = (const float*)d_in[7];
    float* out = (float*)d_out;

    float *vin, *att;
    ull *sqh,*sql,*skh,*skl,*svh,*svl,*w1h,*w1l,*w2h,*w2l,*w3h,*w3l;
    ull *qh,*ql,*kh,*kl,*vh,*vl;
    cudaGetSymbolAddress((void**)&vin, g_vin);
    cudaGetSymbolAddress((void**)&att, g_att);
    cudaGetSymbolAddress((void**)&sqh, g_sqh); cudaGetSymbolAddress((void**)&sql, g_sql);
    cudaGetSymbolAddress((void**)&skh, g_skh); cudaGetSymbolAddress((void**)&skl, g_skl);
    cudaGetSymbolAddress((void**)&svh, g_svh); cudaGetSymbolAddress((void**)&svl, g_svl);
    cudaGetSymbolAddress((void**)&w1h, g_w1h); cudaGetSymbolAddress((void**)&w1l, g_w1l);
    cudaGetSymbolAddress((void**)&w2h, g_w2h); cudaGetSymbolAddress((void**)&w2l, g_w2l);
    cudaGetSymbolAddress((void**)&w3h, g_w3h); cudaGetSymbolAddress((void**)&w3l, g_w3l);
    cudaGetSymbolAddress((void**)&qh,  g_qh);  cudaGetSymbolAddress((void**)&ql,  g_ql);
    cudaGetSymbolAddress((void**)&kh,  g_kh);  cudaGetSymbolAddress((void**)&kl,  g_kl);
    cudaGetSymbolAddress((void**)&vh,  g_vh);  cudaGetSymbolAddress((void**)&vl,  g_vl);

    const int n4i = M_ * D_ / 4;
    const int n4w = D_ * D_ / 4;

    // 1) v_in = LN(seq_v), fused split
    ln_kernel<<<M_, 128>>>(seq_v, nullptr, gamma, beta, vin, svh, svl);
    // 2) split q/k inputs (one launch)
    split_in_kernel<<<2*n4i/256, 256>>>((const float4*)seq_q, sqh, sql,
                                        (const float4*)seq_k, skh, skl, n4i);
    // 3) split weights (one launch)
    split_w_kernel<<<3*n4w/256, 256>>>((const float4*)W1, w1h, w1l,
                                       (const float4*)W2, w2h, w2l,
                                       (const float4*)W3, w3h, w3l, n4w);
    // 4) projections, 3-in-1
    cudaFuncSetAttribute(gemm_tc, cudaFuncAttributeMaxDynamicSharedMemorySize, GEMM_SMEM);
    dim3 ggrid(D_ / 128, M_ / 128, 3);
    gemm_tc<<<ggrid, 256, GEMM_SMEM>>>(
        sqh, sql, w1h, w1l, (__nv_bfloat16*)qh, (__nv_bfloat16*)ql,
        skh, skl, w2h, w2l, (__nv_bfloat16*)kh, (__nv_bfloat16*)kl,
        svh, svl, w3h, w3l, (__nv_bfloat16*)vh, (__nv_bfloat16*)vl);
    // 5) attention (launch #5 -> ncu profiles this)
    cudaFuncSetAttribute(attn_tc, cudaFuncAttributeMaxDynamicSharedMemorySize, ATTN_SMEM);
    attn_tc<<<dim3(S_ / 128, B_ * H_), 256, ATTN_SMEM>>>(qh, ql, kh, kl, vh, vl, att);
    // 6) out = LN(att + v_in)
    ln_kernel<<<M_, 128>>>(att, vin, gamma, beta, out, nullptr, nullptr);
}